// round 7
// baseline (speedup 1.0000x reference)
#include <cuda_runtime.h>
#include <cuda_bf16.h>
#include <cstdint>

#define Bb 4
#define Nn 256
#define Ee 256
#define Hh 16
#define Dd 16
#define FFh 512
#define Ll 5
#define BNE (Bb*Nn*Ee)          // 262144
#define BNF (Bb*Nn*FFh)         // 524288

// ================= device scratch =================
__device__ float g_scaled [Bb*Nn*Nn];
__device__ float g_scaledT[Bb*Nn*Nn];
__device__ float g_mn[Bb], g_mx[Bb];
__device__ float g_alpha[Ll*2*Hh], g_beta[Ll*2*Hh];
__device__ float g_bufA[2*BNE], g_bufB[2*BNE];
__device__ float g_Q[2*BNE], g_K[2*BNE], g_V[2*BNE];
__device__ float g_t1[2*BNE], g_o1[2*BNE];
__device__ float g_P[2*Bb*Hh*Nn*Nn];

// bf16 split activations
__device__ __nv_bfloat16 g_xhA[2*BNE], g_xlA[2*BNE], g_xhB[2*BNE], g_xlB[2*BNE];
__device__ __nv_bfloat16 g_oh[2*BNE],  g_ol[2*BNE];
__device__ __nv_bfloat16 g_o1h[2*BNE], g_o1l[2*BNE];
__device__ __nv_bfloat16 g_ffh[2*BNF], g_ffl[2*BNF];
// bf16 split transposed weights (WT[N,K])
__device__ __nv_bfloat16 g_wqh[10*65536],  g_wql[10*65536];
__device__ __nv_bfloat16 g_wkh[10*65536],  g_wkl[10*65536];
__device__ __nv_bfloat16 g_wvh[10*65536],  g_wvl[10*65536];
__device__ __nv_bfloat16 g_wch[10*65536],  g_wcl[10*65536];
__device__ __nv_bfloat16 g_w1h[10*131072], g_w1l[10*131072];
__device__ __nv_bfloat16 g_w2h[10*131072], g_w2l[10*131072];

// ================= small kernels =================
__global__ void k_minmax(const float* __restrict__ data, float* mn, float* mx)
{
    int b = blockIdx.x, tid = threadIdx.x;
    const float* p = data + (size_t)b*Nn*Nn;
    float lmn = 1e30f, lmx = -1e30f;
    for (int i = tid; i < Nn*Nn; i += 256) { float v = p[i]; lmn = fminf(lmn,v); lmx = fmaxf(lmx,v); }
    __shared__ float smn[256], smx[256];
    smn[tid]=lmn; smx[tid]=lmx; __syncthreads();
    for (int s=128; s; s>>=1){ if (tid<s){ smn[tid]=fminf(smn[tid],smn[tid+s]); smx[tid]=fmaxf(smx[tid],smx[tid+s]); } __syncthreads(); }
    if (!tid){ mn[b]=smn[0]; mx[b]=smx[0]; }
}

__global__ void k_scale(const float* __restrict__ data, const float* __restrict__ mn,
                        const float* __restrict__ mx, float* __restrict__ S, float* __restrict__ ST)
{
    int b = blockIdx.z;
    float m0v = mn[b], r = mx[b]-m0v; if (r == 0.f) r = 1.f;
    float inv = 1.f/r;
    __shared__ float tile[32][33];
    int n0 = blockIdx.y*32, mm0 = blockIdx.x*32;
    int tx = threadIdx.x, ty0 = threadIdx.y;
    #pragma unroll
    for (int i=0;i<4;i++){
        int ty = ty0 + i*8;
        float v = (data[((size_t)b*Nn + n0+ty)*Nn + mm0+tx] - m0v)*inv;
        S[((size_t)b*Nn + n0+ty)*Nn + mm0+tx] = v;
        tile[ty][tx] = v;
    }
    __syncthreads();
    #pragma unroll
    for (int i=0;i<4;i++){
        int ty = ty0 + i*8;
        ST[((size_t)b*Nn + mm0+ty)*Nn + n0+tx] = tile[tx][ty];
    }
}

__global__ void k_ab(const float* __restrict__ Wedge, const float* __restrict__ bedge,
                     const float* __restrict__ Wmix, float* __restrict__ alpha, float* __restrict__ beta)
{
    int ij = blockIdx.x, h = blockIdx.y, lane = threadIdx.x;
    float a = 0.f, bb = 0.f;
    for (int e = lane; e < Ee; e += 32){
        float wm = Wmix[((size_t)ij*Ee + e)*Hh + h];
        a  += Wedge[e]*wm;
        bb += bedge[e]*wm;
    }
    for (int o=16;o;o>>=1){ a += __shfl_xor_sync(0xffffffffu,a,o); bb += __shfl_xor_sync(0xffffffffu,bb,o); }
    if (!lane){ alpha[ij*Hh+h]=a; beta[ij*Hh+h]=bb; }
}

__global__ void k_emb(const float* __restrict__ nr, const float* __restrict__ Wn,
                      const float* __restrict__ bn, float* __restrict__ X,
                      __nv_bfloat16* __restrict__ xh, __nv_bfloat16* __restrict__ xl)
{
    int idx = blockIdx.x*256 + threadIdx.x;
    int e = idx & (Ee-1), bni = idx >> 8;
    float v = nr[bni]*Wn[e] + bn[e];
    X[idx] = v; X[idx + BNE] = v;
    __nv_bfloat16 hi = __float2bfloat16(v);
    __nv_bfloat16 lo = __float2bfloat16(v - __bfloat162float(hi));
    xh[idx]=hi; xh[idx+BNE]=hi;
    xl[idx]=lo; xl[idx+BNE]=lo;
}

// transpose + split: W[K,N] fp32 -> WT_hi/lo[N,K] bf16, grid z = matrix
__global__ void k_tsplit(const float* __restrict__ src, __nv_bfloat16* __restrict__ h,
                         __nv_bfloat16* __restrict__ l, int K, int N)
{
    int mat = blockIdx.z;
    const float* s = src + (size_t)mat*K*N;
    __nv_bfloat16* oh = h + (size_t)mat*K*N;
    __nv_bfloat16* ol = l + (size_t)mat*K*N;
    __shared__ float tile[32][33];
    int n0 = blockIdx.x*32, k0 = blockIdx.y*32;
    int tx = threadIdx.x, ty = threadIdx.y;
    #pragma unroll
    for (int i=0;i<4;i++) tile[ty+i*8][tx] = s[(size_t)(k0+ty+i*8)*N + n0+tx];
    __syncthreads();
    #pragma unroll
    for (int i=0;i<4;i++){
        int n = n0+ty+i*8, k = k0+tx;
        float v = tile[tx][ty+i*8];
        __nv_bfloat16 hi = __float2bfloat16(v);
        oh[(size_t)n*K + k] = hi;
        ol[(size_t)n*K + k] = __float2bfloat16(v - __bfloat162float(hi));
    }
}

// ================= HMMA 3xBF16 GEMM core =================
// C[64,64] tile at (m0,n0): C = A@W, A[M,K] from (ah+al), W as WT[N,K]=(wh+wl)
// 128 threads = 4 warps, warp tile 32x32 (2 m-frags x 4 n-frags of m16n8k16)

#define AS 36   // smem row stride in bf16 (64B data + 8B pad)

__device__ __forceinline__ void hmma(float* c, const uint32_t* a, const uint32_t* b){
    asm volatile("mma.sync.aligned.m16n8k16.row.col.f32.bf16.bf16.f32 "
        "{%0,%1,%2,%3}, {%4,%5,%6,%7}, {%8,%9}, {%0,%1,%2,%3};"
        : "+f"(c[0]), "+f"(c[1]), "+f"(c[2]), "+f"(c[3])
        : "r"(a[0]), "r"(a[1]), "r"(a[2]), "r"(a[3]), "r"(b[0]), "r"(b[1]));
}

__device__ __forceinline__ void tgemm_core(
    const __nv_bfloat16* __restrict__ ah, const __nv_bfloat16* __restrict__ al,
    const __nv_bfloat16* __restrict__ wh, const __nv_bfloat16* __restrict__ wl,
    const float* __restrict__ bias, const float* __restrict__ res,
    float* __restrict__ Cf, __nv_bfloat16* __restrict__ Chi, __nv_bfloat16* __restrict__ Clo,
    int m0, int n0, int Ng, int K, int relu)
{
    __shared__ __nv_bfloat16 sAh[2][64][AS], sAl[2][64][AS];
    __shared__ __nv_bfloat16 sBh[2][64][AS], sBl[2][64][AS];

    int tid = threadIdx.x;
    int lane = tid & 31, w = tid >> 5;
    int wm = (w >> 1)*32, wn = (w & 1)*32;
    int g = lane >> 2, tg = lane & 3;

    float acc[2][4][4];
    #pragma unroll
    for (int mi=0;mi<2;mi++)
        #pragma unroll
        for (int ni=0;ni<4;ni++)
            #pragma unroll
            for (int q=0;q<4;q++) acc[mi][ni][q]=0.f;

    const int nch = K >> 5;            // K chunks of 32
    int lr = tid >> 3, lk = (tid & 7)*4;   // 64 rows x 8 k-quads per 128 threads -> 4 iters

    uint2 rA0[4], rA1[4], rB0[4], rB1[4];
    auto loadRegs = [&](int c){
        #pragma unroll
        for (int it = 0; it < 4; it++){
            int r = lr + it*16;
            size_t aoff = (size_t)(m0 + r)*K + c*32 + lk;
            size_t boff = (size_t)(n0 + r)*K + c*32 + lk;
            rA0[it] = *(const uint2*)(ah + aoff);
            rA1[it] = *(const uint2*)(al + aoff);
            rB0[it] = *(const uint2*)(wh + boff);
            rB1[it] = *(const uint2*)(wl + boff);
        }
    };
    auto storeSmem = [&](int st){
        #pragma unroll
        for (int it = 0; it < 4; it++){
            int r = lr + it*16;
            *(uint2*)&sAh[st][r][lk] = rA0[it];
            *(uint2*)&sAl[st][r][lk] = rA1[it];
            *(uint2*)&sBh[st][r][lk] = rB0[it];
            *(uint2*)&sBl[st][r][lk] = rB1[it];
        }
    };

    loadRegs(0);
    storeSmem(0);
    __syncthreads();

    for (int c = 0; c < nch; c++){
        if (c + 1 < nch) loadRegs(c + 1);
        int st = c & 1;
        #pragma unroll
        for (int ks = 0; ks < 2; ks++){
            int kb = ks*16 + 2*tg;
            uint32_t fah[2][4], fal[2][4];
            #pragma unroll
            for (int mi = 0; mi < 2; mi++){
                int rb = wm + mi*16 + g;
                fah[mi][0] = *(const uint32_t*)&sAh[st][rb  ][kb];
                fah[mi][1] = *(const uint32_t*)&sAh[st][rb+8][kb];
                fah[mi][2] = *(const uint32_t*)&sAh[st][rb  ][kb+8];
                fah[mi][3] = *(const uint32_t*)&sAh[st][rb+8][kb+8];
                fal[mi][0] = *(const uint32_t*)&sAl[st][rb  ][kb];
                fal[mi][1] = *(const uint32_t*)&sAl[st][rb+8][kb];
                fal[mi][2] = *(const uint32_t*)&sAl[st][rb  ][kb+8];
                fal[mi][3] = *(const uint32_t*)&sAl[st][rb+8][kb+8];
            }
            uint32_t fbh[4][2], fbl[4][2];
            #pragma unroll
            for (int ni = 0; ni < 4; ni++){
                int nb = wn + ni*8 + g;
                fbh[ni][0] = *(const uint32_t*)&sBh[st][nb][kb];
                fbh[ni][1] = *(const uint32_t*)&sBh[st][nb][kb+8];
                fbl[ni][0] = *(const uint32_t*)&sBl[st][nb][kb];
                fbl[ni][1] = *(const uint32_t*)&sBl[st][nb][kb+8];
            }
            #pragma unroll
            for (int mi = 0; mi < 2; mi++)
                #pragma unroll
                for (int ni = 0; ni < 4; ni++){
                    hmma(acc[mi][ni], fah[mi], fbh[ni]);
                    hmma(acc[mi][ni], fah[mi], fbl[ni]);
                    hmma(acc[mi][ni], fal[mi], fbh[ni]);
                }
        }
        __syncthreads();
        if (c + 1 < nch){
            storeSmem((c + 1) & 1);
            __syncthreads();
        }
    }

    // epilogue
    #pragma unroll
    for (int mi = 0; mi < 2; mi++){
        #pragma unroll
        for (int ni = 0; ni < 4; ni++){
            int col = n0 + wn + ni*8 + 2*tg;
            float b0 = bias ? bias[col]   : 0.f;
            float b1 = bias ? bias[col+1] : 0.f;
            #pragma unroll
            for (int half = 0; half < 2; half++){
                int m = m0 + wm + mi*16 + g + half*8;
                float v0 = acc[mi][ni][half*2+0] + b0;
                float v1 = acc[mi][ni][half*2+1] + b1;
                if (res){
                    v0 += res[(size_t)m*Ng + col];
                    v1 += res[(size_t)m*Ng + col+1];
                }
                if (relu){ v0 = fmaxf(v0, 0.f); v1 = fmaxf(v1, 0.f); }
                if (Cf){
                    float2 o; o.x = v0; o.y = v1;
                    *(float2*)&Cf[(size_t)m*Ng + col] = o;
                }
                if (Chi){
                    __nv_bfloat16 h0 = __float2bfloat16(v0), h1 = __float2bfloat16(v1);
                    __nv_bfloat162 hp; hp.x = h0; hp.y = h1;
                    __nv_bfloat162 lp;
                    lp.x = __float2bfloat16(v0 - __bfloat162float(h0));
                    lp.y = __float2bfloat16(v1 - __bfloat162float(h1));
                    *(__nv_bfloat162*)&Chi[(size_t)m*Ng + col] = hp;
                    *(__nv_bfloat162*)&Clo[(size_t)m*Ng + col] = lp;
                }
            }
        }
    }
}

// fused QKV: grid (12, 16, 2): wsel = x>>2 (0=Q,1=K,2=V), nt = x&3
__global__ void __launch_bounds__(128) k_tqkv(
                       const __nv_bfloat16* __restrict__ xh, const __nv_bfloat16* __restrict__ xl,
                       const __nv_bfloat16* wqh, const __nv_bfloat16* wql,
                       const __nv_bfloat16* wkh, const __nv_bfloat16* wkl,
                       const __nv_bfloat16* wvh, const __nv_bfloat16* wvl,
                       float* Q, float* K, float* V)
{
    int wsel = blockIdx.x >> 2, nt = blockIdx.x & 3, z = blockIdx.z;
    int az = wsel ? (1 - z) : z;
    const __nv_bfloat16 *wh, *wl; float* out;
    if (wsel == 0){ wh = wqh; wl = wql; out = Q; }
    else if (wsel == 1){ wh = wkh; wl = wkl; out = K; }
    else { wh = wvh; wl = wvl; out = V; }
    tgemm_core(xh + (size_t)az*BNE, xl + (size_t)az*BNE,
               wh + (size_t)z*65536, wl + (size_t)z*65536,
               nullptr, nullptr,
               out + (size_t)z*BNE, nullptr, nullptr,
               blockIdx.y*64, nt*64, 256, 256, 0);
}

// generic: grid (Ng/64, 16, 2)
__global__ void __launch_bounds__(128) k_tgemm(
                        const __nv_bfloat16* __restrict__ ah, const __nv_bfloat16* __restrict__ al, int aStrideZ,
                        const __nv_bfloat16* __restrict__ wh, const __nv_bfloat16* __restrict__ wl, int wStrideZ,
                        const float* bias, int biasStrideZ,
                        const float* res, int resStrideZ,
                        float* Cf, __nv_bfloat16* Chi, __nv_bfloat16* Clo, int cStrideZ,
                        int Ng, int K, int relu)
{
    int z = blockIdx.z;
    tgemm_core(ah + (size_t)z*aStrideZ, al + (size_t)z*aStrideZ,
               wh + (size_t)z*wStrideZ, wl + (size_t)z*wStrideZ,
               bias ? bias + (size_t)z*biasStrideZ : nullptr,
               res  ? res  + (size_t)z*resStrideZ  : nullptr,
               Cf  ? Cf  + (size_t)z*cStrideZ : nullptr,
               Chi ? Chi + (size_t)z*cStrideZ : nullptr,
               Clo ? Clo + (size_t)z*cStrideZ : nullptr,
               blockIdx.y*64, blockIdx.x*64, Ng, K, relu);
}

// ================= attention =================
__global__ void k_score(const float* __restrict__ Q, const float* __restrict__ K,
                        const float* __restrict__ scaled, const float* __restrict__ scaledT,
                        const float* __restrict__ alpha, const float* __restrict__ beta,
                        float* __restrict__ P)
{
    int rg = blockIdx.x;
    int bh = blockIdx.y;
    int z  = blockIdx.z;
    int b = bh >> 4, h = bh & 15;
    const float* Sc = z ? scaledT : scaled;
    size_t qkbase = ((size_t)(z*Bb + b))*Nn*Ee;
    const float* Qp = Q + qkbase + (size_t)rg*32*Ee + h*16;
    const float* Kp = K + qkbase + h*16;
    float al = alpha[z*Hh + h], be = beta[z*Hh + h];

    __shared__ float qs[32][17];
    __shared__ float Ks[16][260];
    int tid = threadIdx.x;
    {
        int d = tid & 15, mg = tid >> 4;
        #pragma unroll
        for (int i = 0; i < 16; i++){
            int m = mg + i*16;
            Ks[d][m] = Kp[(size_t)m*Ee + d];
        }
        qs[mg][d]      = Qp[(size_t)mg*Ee + d];
        qs[mg+16][d]   = Qp[(size_t)(mg+16)*Ee + d];
    }
    __syncthreads();

    int n = tid >> 3, s = tid & 7, m0 = s*32;
    const float* srow = Sc + ((size_t)b*Nn + rg*32 + n)*Nn + m0;
    float acc[32];
    #pragma unroll
    for (int mm = 0; mm < 32; mm += 4){
        float4 sv = *(const float4*)&srow[mm];
        acc[mm+0] = sv.x*al + be;
        acc[mm+1] = sv.y*al + be;
        acc[mm+2] = sv.z*al + be;
        acc[mm+3] = sv.w*al + be;
    }
    #pragma unroll
    for (int d = 0; d < 16; d++){
        float qv = qs[n][d] * 0.25f;
        #pragma unroll
        for (int mm = 0; mm < 32; mm += 4){
            float4 kv = *(const float4*)&Ks[d][m0+mm];
            acc[mm+0] += qv*kv.x; acc[mm+1] += qv*kv.y;
            acc[mm+2] += qv*kv.z; acc[mm+3] += qv*kv.w;
        }
    }
    float mxv = -1e30f;
    #pragma unroll
    for (int mm=0;mm<32;mm++) mxv = fmaxf(mxv, acc[mm]);
    mxv = fmaxf(mxv, __shfl_xor_sync(0xffffffffu, mxv, 1));
    mxv = fmaxf(mxv, __shfl_xor_sync(0xffffffffu, mxv, 2));
    mxv = fmaxf(mxv, __shfl_xor_sync(0xffffffffu, mxv, 4));
    float sum = 0.f;
    #pragma unroll
    for (int mm=0;mm<32;mm++){ acc[mm] = __expf(acc[mm]-mxv); sum += acc[mm]; }
    sum += __shfl_xor_sync(0xffffffffu, sum, 1);
    sum += __shfl_xor_sync(0xffffffffu, sum, 2);
    sum += __shfl_xor_sync(0xffffffffu, sum, 4);
    float inv = 1.f/sum;
    float* prow = P + (((size_t)(z*Bb+b)*Hh + h)*Nn + rg*32 + n)*Nn + m0;
    #pragma unroll
    for (int mm=0; mm<32; mm+=4){
        float4 o = make_float4(acc[mm]*inv, acc[mm+1]*inv, acc[mm+2]*inv, acc[mm+3]*inv);
        *(float4*)&prow[mm] = o;
    }
}

// P @ V -> O (bf16 hi/lo split out, consumed by comb tensor GEMM)
__global__ void k_pv(const float* __restrict__ P, const float* __restrict__ V,
                     __nv_bfloat16* __restrict__ Oh, __nv_bfloat16* __restrict__ Ol)
{
    int nt = blockIdx.x;
    int bh = blockIdx.y;
    int z  = blockIdx.z;
    int b = bh >> 4, h = bh & 15;
    size_t vbase = ((size_t)(z*Bb+b))*Nn*Ee + h*16;
    const float* Pp = P + (((size_t)(z*Bb+b)*Hh + h)*Nn + nt*64)*Nn;

    __shared__ float Pm[64][68];
    __shared__ float Vs[64][17];
    int tid = threadIdx.x;
    int d = tid & 15, nl = tid >> 4;
    float acc[4] = {0.f,0.f,0.f,0.f};

    for (int mc = 0; mc < 4; mc++){
        {
            int r = tid >> 2, c4 = (tid & 3)*16;
            const float* src = Pp + (size_t)r*Nn + mc*64 + c4;
            #pragma unroll
            for (int u=0;u<4;u++){
                float4 v4 = *(const float4*)&src[u*4];
                *(float4*)&Pm[r][c4 + u*4] = v4;
            }
            int mg = tid >> 4;
            #pragma unroll
            for (int i=0;i<4;i++){
                int m = mg + i*16;
                Vs[m][d] = V[vbase + (size_t)(mc*64 + m)*Ee + d];
            }
        }
        __syncthreads();
        #pragma unroll 8
        for (int mm = 0; mm < 64; mm++){
            float vv = Vs[mm][d];
            acc[0] += Pm[nl     ][mm]*vv;
            acc[1] += Pm[nl + 16][mm]*vv;
            acc[2] += Pm[nl + 32][mm]*vv;
            acc[3] += Pm[nl + 48][mm]*vv;
        }
        __syncthreads();
    }
    #pragma unroll
    for (int i=0;i<4;i++){
        float v = acc[i];
        __nv_bfloat16 hi = __float2bfloat16(v);
        size_t off = vbase + (size_t)(nt*64 + nl + i*16)*Ee + d;
        Oh[off] = hi;
        Ol[off] = __float2bfloat16(v - __bfloat162float(hi));
    }
}

// instance norm + bf16 split output
__global__ void k_inorm(const float* __restrict__ X, float* __restrict__ Y,
                        const float* __restrict__ wbase, const float* __restrict__ bbase,
                        __nv_bfloat16* __restrict__ Yh, __nv_bfloat16* __restrict__ Yl)
{
    int z = blockIdx.z, b = blockIdx.x, e0 = blockIdx.y*64;
    const float* w = wbase + (size_t)z*Ee;
    const float* bp = bbase + (size_t)z*Ee;
    int tid = threadIdx.x;
    int el = tid & 63, nc = tid >> 6;
    size_t base = ((size_t)(z*Bb+b))*Nn*Ee;
    float s = 0.f, ss = 0.f;
    for (int n = nc; n < Nn; n += 4){
        float v = X[base + (size_t)n*Ee + e0 + el];
        s += v; ss += v*v;
    }
    __shared__ float sh_s[4][64], sh_ss[4][64];
    __shared__ float muA[64], invA[64];
    sh_s[nc][el] = s; sh_ss[nc][el] = ss;
    __syncthreads();
    if (nc == 0){
        float S  = sh_s[0][el]+sh_s[1][el]+sh_s[2][el]+sh_s[3][el];
        float SS = sh_ss[0][el]+sh_ss[1][el]+sh_ss[2][el]+sh_ss[3][el];
        float mu = S*(1.f/Nn);
        float var = SS*(1.f/Nn) - mu*mu;
        muA[el] = mu;
        invA[el] = rsqrtf(var + 1e-5f);
    }
    __syncthreads();
    float mu = muA[el];
    float sc = invA[el]*w[e0+el];
    float sb = bp[e0+el];
    for (int n = nc; n < Nn; n += 4){
        size_t off = base + (size_t)n*Ee + e0 + el;
        float y = (X[off]-mu)*sc + sb;
        Y[off] = y;
        __nv_bfloat16 hi = __float2bfloat16(y);
        Yh[off] = hi;
        Yl[off] = __float2bfloat16(y - __bfloat162float(hi));
    }
}

__global__ void k_copy(float* __restrict__ dst, const float* __restrict__ src, int n)
{
    int i = blockIdx.x*256 + threadIdx.x;
    if (i < n) dst[i] = src[i];
}

// ================= host launcher =================
extern "C" void kernel_launch(void* const* d_in, const int* in_sizes, int n_in,
                              void* d_out, int out_size)
{
    const float* data      = (const float*)d_in[0];
    const float* node_rand = (const float*)d_in[1];
    const float* Wnode = (const float*)d_in[2];
    const float* bnode = (const float*)d_in[3];
    const float* Wedge = (const float*)d_in[4];
    const float* bedge = (const float*)d_in[5];
    const float* Wq    = (const float*)d_in[6];
    const float* Wk    = (const float*)d_in[7];
    const float* Wv    = (const float*)d_in[8];
    const float* Wcomb = (const float*)d_in[9];
    const float* bcomb = (const float*)d_in[10];
    const float* n1w   = (const float*)d_in[11];
    const float* n1b   = (const float*)d_in[12];
    const float* W1    = (const float*)d_in[13];
    const float* b1    = (const float*)d_in[14];
    const float* W2    = (const float*)d_in[15];
    const float* b2    = (const float*)d_in[16];
    const float* n2w   = (const float*)d_in[17];
    const float* n2b   = (const float*)d_in[18];
    const float* Wmix  = (const float*)d_in[19];

    float *scaled, *scaledT, *mn, *mx, *alpha, *beta;
    float *bufA, *bufB, *Qb, *Kb, *Vb, *t1, *o1, *Pb;
    __nv_bfloat16 *xhA,*xlA,*xhB,*xlB,*oh,*ol,*o1h,*o1l,*ffh,*ffl;
    __nv_bfloat16 *wqh,*wql,*wkh,*wkl,*wvh,*wvl,*wch,*wcl,*w1h,*w1l,*w2h,*w2l;
    cudaGetSymbolAddress((void**)&scaled,  g_scaled);
    cudaGetSymbolAddress((void**)&scaledT, g_scaledT);
    cudaGetSymbolAddress((void**)&mn,      g_mn);
    cudaGetSymbolAddress((void**)&mx,      g_mx);
    cudaGetSymbolAddress((void**)&alpha,   g_alpha);
    cudaGetSymbolAddress((void**)&beta,    g_beta);
    cudaGetSymbolAddress((void**)&bufA,    g_bufA);
    cudaGetSymbolAddress((void**)&bufB,    g_bufB);
    cudaGetSymbolAddress((void**)&Qb,      g_Q);
    cudaGetSymbolAddress((void**)&Kb,      g_K);
    cudaGetSymbolAddress((void**)&Vb,      g_V);
    cudaGetSymbolAddress((void**)&t1,      g_t1);
    cudaGetSymbolAddress((void**)&o1,      g_o1);
    cudaGetSymbolAddress((void**)&Pb,      g_P);
    cudaGetSymbolAddress((void**)&xhA, g_xhA); cudaGetSymbolAddress((void**)&xlA, g_xlA);
    cudaGetSymbolAddress((void**)&xhB, g_xhB); cudaGetSymbolAddress((void**)&xlB, g_xlB);
    cudaGetSymbolAddress((void**)&oh,  g_oh);  cudaGetSymbolAddress((void**)&ol,  g_ol);
    cudaGetSymbolAddress((void**)&o1h, g_o1h); cudaGetSymbolAddress((void**)&o1l, g_o1l);
    cudaGetSymbolAddress((void**)&ffh, g_ffh); cudaGetSymbolAddress((void**)&ffl, g_ffl);
    cudaGetSymbolAddress((void**)&wqh, g_wqh); cudaGetSymbolAddress((void**)&wql, g_wql);
    cudaGetSymbolAddress((void**)&wkh, g_wkh); cudaGetSymbolAddress((void**)&wkl, g_wkl);
    cudaGetSymbolAddress((void**)&wvh, g_wvh); cudaGetSymbolAddress((void**)&wvl, g_wvl);
    cudaGetSymbolAddress((void**)&wch, g_wch); cudaGetSymbolAddress((void**)&wcl, g_wcl);
    cudaGetSymbolAddress((void**)&w1h, g_w1h); cudaGetSymbolAddress((void**)&w1l, g_w1l);
    cudaGetSymbolAddress((void**)&w2h, g_w2h); cudaGetSymbolAddress((void**)&w2l, g_w2l);

    // setup
    k_minmax<<<Bb, 256>>>(data, mn, mx);
    k_scale<<<dim3(8,8,Bb), dim3(32,8)>>>(data, mn, mx, scaled, scaledT);
    k_ab<<<dim3(Ll*2, Hh), 32>>>(Wedge, bedge, Wmix, alpha, beta);
    k_emb<<<BNE/256, 256>>>(node_rand, Wnode, bnode, bufA, xhA, xlA);
    // weight transpose+split (10 matrices each)
    k_tsplit<<<dim3(8,8,10),  dim3(32,8)>>>(Wq,    wqh, wql, 256, 256);
    k_tsplit<<<dim3(8,8,10),  dim3(32,8)>>>(Wk,    wkh, wkl, 256, 256);
    k_tsplit<<<dim3(8,8,10),  dim3(32,8)>>>(Wv,    wvh, wvl, 256, 256);
    k_tsplit<<<dim3(8,8,10),  dim3(32,8)>>>(Wcomb, wch, wcl, 256, 256);
    k_tsplit<<<dim3(16,8,10), dim3(32,8)>>>(W1,    w1h, w1l, 256, 512);
    k_tsplit<<<dim3(8,16,10), dim3(32,8)>>>(W2,    w2h, w2l, 512, 256);

    for (int i = 0; i < Ll; i++){
        float* Xc = (i & 1) ? bufB : bufA;
        __nv_bfloat16* xhc = (i & 1) ? xhB : xhA;
        __nv_bfloat16* xlc = (i & 1) ? xlB : xlA;
        __nv_bfloat16* xhn = (i & 1) ? xhA : xhB;
        __nv_bfloat16* xln = (i & 1) ? xlA : xlB;
        float* Xn = (i & 1) ? bufA : bufB;
        size_t w256 = (size_t)i*2*65536;
        size_t w512 = (size_t)i*2*131072;
        const float* bcomb_i = bcomb + (size_t)i*2*Ee;
        const float* b1_i    = b1    + (size_t)i*2*FFh;
        const float* b2_i    = b2    + (size_t)i*2*Ee;

        // Q/K/V tensor GEMMs (fused launch)
        k_tqkv<<<dim3(12,16,2), 128>>>(xhc, xlc,
            wqh + w256, wql + w256, wkh + w256, wkl + w256, wvh + w256, wvl + w256,
            Qb, Kb, Vb);
        // attention
        k_score<<<dim3(8, Bb*Hh, 2), 256>>>(Qb, Kb, scaled, scaledT,
            alpha + i*2*Hh, beta + i*2*Hh, Pb);
        k_pv<<<dim3(4, Bb*Hh, 2), 256>>>(Pb, Vb, oh, ol);
        // t1 = O @ Wcomb + bcomb + Xc
        k_tgemm<<<dim3(4,16,2), 128>>>(oh, ol, BNE, wch + w256, wcl + w256, 65536,
            bcomb_i, Ee, Xc, BNE, t1, nullptr, nullptr, BNE, 256, 256, 0);
        k_inorm<<<dim3(Bb,4,2), 256>>>(t1, o1, n1w + (size_t)i*2*Ee, n1b + (size_t)i*2*Ee, o1h, o1l);
        // ff = relu(o1 @ W1 + b1)  -> bf16 split only
        k_tgemm<<<dim3(8,16,2), 128>>>(o1h, o1l, BNE, w1h + w512, w1l + w512, 131072,
            b1_i, FFh, nullptr, 0, nullptr, ffh, ffl, BNF, 512, 256, 1);
        // t1 = ff @ W2 + b2 + o1
        k_tgemm<<<dim3(4,16,2), 128>>>(ffh, ffl, BNF, w2h + w512, w2l + w512, 131072,
            b2_i, Ee, o1, BNE, t1, nullptr, nullptr, BNE, 256, 512, 0);
        k_inorm<<<dim3(Bb,4,2), 256>>>(t1, Xn, n2w + (size_t)i*2*Ee, n2b + (size_t)i*2*Ee, xhn, xln);
    }

    int total = 2*BNE;
    if (out_size < total) total = out_size;
    k_copy<<<(total+255)/256, 256>>>((float*)d_out, bufB, total);
}

// round 8
// speedup vs baseline: 2.0029x; 2.0029x over previous
#include <cuda_runtime.h>
#include <cuda_bf16.h>
#include <cstdint>

#define Bb 4
#define Nn 256
#define Ee 256
#define Hh 16
#define Dd 16
#define FFh 512
#define Ll 5
#define BNE (Bb*Nn*Ee)          // 262144
#define BNF (Bb*Nn*FFh)         // 524288

// ================= device scratch =================
__device__ float g_scaled [Bb*Nn*Nn];
__device__ float g_scaledT[Bb*Nn*Nn];
__device__ float g_mn[Bb], g_mx[Bb];
__device__ float g_alpha[Ll*2*Hh], g_beta[Ll*2*Hh];
__device__ float g_bufA[2*BNE], g_bufB[2*BNE];
__device__ float g_Q[2*BNE], g_K[2*BNE], g_V[2*BNE];
__device__ float g_t1[2*BNE], g_o1[2*BNE];

// bf16 split activations
__device__ __nv_bfloat16 g_xhA[2*BNE], g_xlA[2*BNE], g_xhB[2*BNE], g_xlB[2*BNE];
__device__ __nv_bfloat16 g_oh[2*BNE],  g_ol[2*BNE];
__device__ __nv_bfloat16 g_o1h[2*BNE], g_o1l[2*BNE];
__device__ __nv_bfloat16 g_ffh[2*BNF], g_ffl[2*BNF];
// bf16 split transposed weights (WT[N,K])
__device__ __nv_bfloat16 g_wqh[10*65536],  g_wql[10*65536];
__device__ __nv_bfloat16 g_wkh[10*65536],  g_wkl[10*65536];
__device__ __nv_bfloat16 g_wvh[10*65536],  g_wvl[10*65536];
__device__ __nv_bfloat16 g_wch[10*65536],  g_wcl[10*65536];
__device__ __nv_bfloat16 g_w1h[10*131072], g_w1l[10*131072];
__device__ __nv_bfloat16 g_w2h[10*131072], g_w2l[10*131072];

// ================= small kernels =================
__global__ void k_minmax(const float* __restrict__ data, float* mn, float* mx)
{
    int b = blockIdx.x, tid = threadIdx.x;
    const float* p = data + (size_t)b*Nn*Nn;
    float lmn = 1e30f, lmx = -1e30f;
    for (int i = tid; i < Nn*Nn; i += 256) { float v = p[i]; lmn = fminf(lmn,v); lmx = fmaxf(lmx,v); }
    __shared__ float smn[256], smx[256];
    smn[tid]=lmn; smx[tid]=lmx; __syncthreads();
    for (int s=128; s; s>>=1){ if (tid<s){ smn[tid]=fminf(smn[tid],smn[tid+s]); smx[tid]=fmaxf(smx[tid],smx[tid+s]); } __syncthreads(); }
    if (!tid){ mn[b]=smn[0]; mx[b]=smx[0]; }
}

__global__ void k_scale(const float* __restrict__ data, const float* __restrict__ mn,
                        const float* __restrict__ mx, float* __restrict__ S, float* __restrict__ ST)
{
    int b = blockIdx.z;
    float m0v = mn[b], r = mx[b]-m0v; if (r == 0.f) r = 1.f;
    float inv = 1.f/r;
    __shared__ float tile[32][33];
    int n0 = blockIdx.y*32, mm0 = blockIdx.x*32;
    int tx = threadIdx.x, ty0 = threadIdx.y;
    #pragma unroll
    for (int i=0;i<4;i++){
        int ty = ty0 + i*8;
        float v = (data[((size_t)b*Nn + n0+ty)*Nn + mm0+tx] - m0v)*inv;
        S[((size_t)b*Nn + n0+ty)*Nn + mm0+tx] = v;
        tile[ty][tx] = v;
    }
    __syncthreads();
    #pragma unroll
    for (int i=0;i<4;i++){
        int ty = ty0 + i*8;
        ST[((size_t)b*Nn + mm0+ty)*Nn + n0+tx] = tile[tx][ty];
    }
}

__global__ void k_ab(const float* __restrict__ Wedge, const float* __restrict__ bedge,
                     const float* __restrict__ Wmix, float* __restrict__ alpha, float* __restrict__ beta)
{
    int ij = blockIdx.x, h = blockIdx.y, lane = threadIdx.x;
    float a = 0.f, bb = 0.f;
    for (int e = lane; e < Ee; e += 32){
        float wm = Wmix[((size_t)ij*Ee + e)*Hh + h];
        a  += Wedge[e]*wm;
        bb += bedge[e]*wm;
    }
    for (int o=16;o;o>>=1){ a += __shfl_xor_sync(0xffffffffu,a,o); bb += __shfl_xor_sync(0xffffffffu,bb,o); }
    if (!lane){ alpha[ij*Hh+h]=a; beta[ij*Hh+h]=bb; }
}

__global__ void k_emb(const float* __restrict__ nr, const float* __restrict__ Wn,
                      const float* __restrict__ bn, float* __restrict__ X,
                      __nv_bfloat16* __restrict__ xh, __nv_bfloat16* __restrict__ xl)
{
    int idx = blockIdx.x*256 + threadIdx.x;
    int e = idx & (Ee-1), bni = idx >> 8;
    float v = nr[bni]*Wn[e] + bn[e];
    X[idx] = v; X[idx + BNE] = v;
    __nv_bfloat16 hi = __float2bfloat16(v);
    __nv_bfloat16 lo = __float2bfloat16(v - __bfloat162float(hi));
    xh[idx]=hi; xh[idx+BNE]=hi;
    xl[idx]=lo; xl[idx+BNE]=lo;
}

// transpose + split: W[K,N] fp32 -> WT_hi/lo[N,K] bf16, grid z = matrix
__global__ void k_tsplit(const float* __restrict__ src, __nv_bfloat16* __restrict__ h,
                         __nv_bfloat16* __restrict__ l, int K, int N)
{
    int mat = blockIdx.z;
    const float* s = src + (size_t)mat*K*N;
    __nv_bfloat16* oh = h + (size_t)mat*K*N;
    __nv_bfloat16* ol = l + (size_t)mat*K*N;
    __shared__ float tile[32][33];
    int n0 = blockIdx.x*32, k0 = blockIdx.y*32;
    int tx = threadIdx.x, ty = threadIdx.y;
    #pragma unroll
    for (int i=0;i<4;i++) tile[ty+i*8][tx] = s[(size_t)(k0+ty+i*8)*N + n0+tx];
    __syncthreads();
    #pragma unroll
    for (int i=0;i<4;i++){
        int n = n0+ty+i*8, k = k0+tx;
        float v = tile[tx][ty+i*8];
        __nv_bfloat16 hi = __float2bfloat16(v);
        oh[(size_t)n*K + k] = hi;
        ol[(size_t)n*K + k] = __float2bfloat16(v - __bfloat162float(hi));
    }
}

// ================= HMMA 3xBF16 GEMM core =================
#define AS 36   // smem row stride in bf16 (64B data + 8B pad)

__device__ __forceinline__ void hmma(float* c, const uint32_t* a, const uint32_t* b){
    asm volatile("mma.sync.aligned.m16n8k16.row.col.f32.bf16.bf16.f32 "
        "{%0,%1,%2,%3}, {%4,%5,%6,%7}, {%8,%9}, {%0,%1,%2,%3};"
        : "+f"(c[0]), "+f"(c[1]), "+f"(c[2]), "+f"(c[3])
        : "r"(a[0]), "r"(a[1]), "r"(a[2]), "r"(a[3]), "r"(b[0]), "r"(b[1]));
}

__device__ __forceinline__ void tgemm_core(
    const __nv_bfloat16* __restrict__ ah, const __nv_bfloat16* __restrict__ al,
    const __nv_bfloat16* __restrict__ wh, const __nv_bfloat16* __restrict__ wl,
    const float* __restrict__ bias, const float* __restrict__ res,
    float* __restrict__ Cf, __nv_bfloat16* __restrict__ Chi, __nv_bfloat16* __restrict__ Clo,
    int m0, int n0, int Ng, int K, int relu)
{
    __shared__ __nv_bfloat16 sAh[2][64][AS], sAl[2][64][AS];
    __shared__ __nv_bfloat16 sBh[2][64][AS], sBl[2][64][AS];

    int tid = threadIdx.x;
    int lane = tid & 31, w = tid >> 5;
    int wm = (w >> 1)*32, wn = (w & 1)*32;
    int g = lane >> 2, tg = lane & 3;

    float acc[2][4][4];
    #pragma unroll
    for (int mi=0;mi<2;mi++)
        #pragma unroll
        for (int ni=0;ni<4;ni++)
            #pragma unroll
            for (int q=0;q<4;q++) acc[mi][ni][q]=0.f;

    const int nch = K >> 5;
    int lr = tid >> 3, lk = (tid & 7)*4;

    uint2 rA0[4], rA1[4], rB0[4], rB1[4];
    auto loadRegs = [&](int c){
        #pragma unroll
        for (int it = 0; it < 4; it++){
            int r = lr + it*16;
            size_t aoff = (size_t)(m0 + r)*K + c*32 + lk;
            size_t boff = (size_t)(n0 + r)*K + c*32 + lk;
            rA0[it] = *(const uint2*)(ah + aoff);
            rA1[it] = *(const uint2*)(al + aoff);
            rB0[it] = *(const uint2*)(wh + boff);
            rB1[it] = *(const uint2*)(wl + boff);
        }
    };
    auto storeSmem = [&](int st){
        #pragma unroll
        for (int it = 0; it < 4; it++){
            int r = lr + it*16;
            *(uint2*)&sAh[st][r][lk] = rA0[it];
            *(uint2*)&sAl[st][r][lk] = rA1[it];
            *(uint2*)&sBh[st][r][lk] = rB0[it];
            *(uint2*)&sBl[st][r][lk] = rB1[it];
        }
    };

    loadRegs(0);
    storeSmem(0);
    __syncthreads();

    for (int c = 0; c < nch; c++){
        if (c + 1 < nch) loadRegs(c + 1);
        int st = c & 1;
        #pragma unroll
        for (int ks = 0; ks < 2; ks++){
            int kb = ks*16 + 2*tg;
            uint32_t fah[2][4], fal[2][4];
            #pragma unroll
            for (int mi = 0; mi < 2; mi++){
                int rb = wm + mi*16 + g;
                fah[mi][0] = *(const uint32_t*)&sAh[st][rb  ][kb];
                fah[mi][1] = *(const uint32_t*)&sAh[st][rb+8][kb];
                fah[mi][2] = *(const uint32_t*)&sAh[st][rb  ][kb+8];
                fah[mi][3] = *(const uint32_t*)&sAh[st][rb+8][kb+8];
                fal[mi][0] = *(const uint32_t*)&sAl[st][rb  ][kb];
                fal[mi][1] = *(const uint32_t*)&sAl[st][rb+8][kb];
                fal[mi][2] = *(const uint32_t*)&sAl[st][rb  ][kb+8];
                fal[mi][3] = *(const uint32_t*)&sAl[st][rb+8][kb+8];
            }
            uint32_t fbh[4][2], fbl[4][2];
            #pragma unroll
            for (int ni = 0; ni < 4; ni++){
                int nb = wn + ni*8 + g;
                fbh[ni][0] = *(const uint32_t*)&sBh[st][nb][kb];
                fbh[ni][1] = *(const uint32_t*)&sBh[st][nb][kb+8];
                fbl[ni][0] = *(const uint32_t*)&sBl[st][nb][kb];
                fbl[ni][1] = *(const uint32_t*)&sBl[st][nb][kb+8];
            }
            #pragma unroll
            for (int mi = 0; mi < 2; mi++)
                #pragma unroll
                for (int ni = 0; ni < 4; ni++){
                    hmma(acc[mi][ni], fah[mi], fbh[ni]);
                    hmma(acc[mi][ni], fah[mi], fbl[ni]);
                    hmma(acc[mi][ni], fal[mi], fbh[ni]);
                }
        }
        __syncthreads();
        if (c + 1 < nch){
            storeSmem((c + 1) & 1);
            __syncthreads();
        }
    }

    #pragma unroll
    for (int mi = 0; mi < 2; mi++){
        #pragma unroll
        for (int ni = 0; ni < 4; ni++){
            int col = n0 + wn + ni*8 + 2*tg;
            float b0 = bias ? bias[col]   : 0.f;
            float b1 = bias ? bias[col+1] : 0.f;
            #pragma unroll
            for (int half = 0; half < 2; half++){
                int m = m0 + wm + mi*16 + g + half*8;
                float v0 = acc[mi][ni][half*2+0] + b0;
                float v1 = acc[mi][ni][half*2+1] + b1;
                if (res){
                    v0 += res[(size_t)m*Ng + col];
                    v1 += res[(size_t)m*Ng + col+1];
                }
                if (relu){ v0 = fmaxf(v0, 0.f); v1 = fmaxf(v1, 0.f); }
                if (Cf){
                    float2 o; o.x = v0; o.y = v1;
                    *(float2*)&Cf[(size_t)m*Ng + col] = o;
                }
                if (Chi){
                    __nv_bfloat16 h0 = __float2bfloat16(v0), h1 = __float2bfloat16(v1);
                    __nv_bfloat162 hp; hp.x = h0; hp.y = h1;
                    __nv_bfloat162 lp;
                    lp.x = __float2bfloat16(v0 - __bfloat162float(h0));
                    lp.y = __float2bfloat16(v1 - __bfloat162float(h1));
                    *(__nv_bfloat162*)&Chi[(size_t)m*Ng + col] = hp;
                    *(__nv_bfloat162*)&Clo[(size_t)m*Ng + col] = lp;
                }
            }
        }
    }
}

// fused QKV: grid (12, 16, 2): wsel = x>>2 (0=Q,1=K,2=V), nt = x&3
__global__ void __launch_bounds__(128) k_tqkv(
                       const __nv_bfloat16* __restrict__ xh, const __nv_bfloat16* __restrict__ xl,
                       const __nv_bfloat16* wqh, const __nv_bfloat16* wql,
                       const __nv_bfloat16* wkh, const __nv_bfloat16* wkl,
                       const __nv_bfloat16* wvh, const __nv_bfloat16* wvl,
                       float* Q, float* K, float* V)
{
    int wsel = blockIdx.x >> 2, nt = blockIdx.x & 3, z = blockIdx.z;
    int az = wsel ? (1 - z) : z;
    const __nv_bfloat16 *wh, *wl; float* out;
    if (wsel == 0){ wh = wqh; wl = wql; out = Q; }
    else if (wsel == 1){ wh = wkh; wl = wkl; out = K; }
    else { wh = wvh; wl = wvl; out = V; }
    tgemm_core(xh + (size_t)az*BNE, xl + (size_t)az*BNE,
               wh + (size_t)z*65536, wl + (size_t)z*65536,
               nullptr, nullptr,
               out + (size_t)z*BNE, nullptr, nullptr,
               blockIdx.y*64, nt*64, 256, 256, 0);
}

// generic: grid (Ng/64, 16, 2)
__global__ void __launch_bounds__(128) k_tgemm(
                        const __nv_bfloat16* __restrict__ ah, const __nv_bfloat16* __restrict__ al, int aStrideZ,
                        const __nv_bfloat16* __restrict__ wh, const __nv_bfloat16* __restrict__ wl, int wStrideZ,
                        const float* bias, int biasStrideZ,
                        const float* res, int resStrideZ,
                        float* Cf, __nv_bfloat16* Chi, __nv_bfloat16* Clo, int cStrideZ,
                        int Ng, int K, int relu)
{
    int z = blockIdx.z;
    tgemm_core(ah + (size_t)z*aStrideZ, al + (size_t)z*aStrideZ,
               wh + (size_t)z*wStrideZ, wl + (size_t)z*wStrideZ,
               bias ? bias + (size_t)z*biasStrideZ : nullptr,
               res  ? res  + (size_t)z*resStrideZ  : nullptr,
               Cf  ? Cf  + (size_t)z*cStrideZ : nullptr,
               Chi ? Chi + (size_t)z*cStrideZ : nullptr,
               Clo ? Clo + (size_t)z*cStrideZ : nullptr,
               blockIdx.y*64, blockIdx.x*64, Ng, K, relu);
}

// ================= fused attention: score + bias + softmax + PV =================
// grid (8, Bb*Hh, 2), 256 threads.
// thread (n2 = tid>>4, s16 = tid&15): rows {rg*32+n2, +16}, m-segment [s16*16, +16)
// K/V staged [256][17] with circular slot (d + (m>>4)) & 15 -> conflict-free reads.
__global__ void __launch_bounds__(256) k_attn(
    const float* __restrict__ Q, const float* __restrict__ Kg, const float* __restrict__ Vg,
    const float* __restrict__ scaled, const float* __restrict__ scaledT,
    const float* __restrict__ alpha, const float* __restrict__ beta,
    __nv_bfloat16* __restrict__ Oh, __nv_bfloat16* __restrict__ Ol)
{
    __shared__ float qs[32][17];
    __shared__ float Vs[256][17];
    __shared__ float kred[8*545];   // Ks[256][17]=4352 floats, later red[8][545]
    __shared__ float sminv[32];

    int rg = blockIdx.x, bh = blockIdx.y, z = blockIdx.z;
    int b = bh >> 4, h = bh & 15;
    const float* Sc = z ? scaledT : scaled;
    size_t base = ((size_t)(z*Bb+b))*(size_t)Nn*Ee;
    const float* Kp = Kg + base + h*16;
    const float* Vp = Vg + base + h*16;
    const float* Qp = Q  + base + (size_t)rg*32*Ee + h*16;
    float al = alpha[z*Hh+h], be = beta[z*Hh+h];
    int tid = threadIdx.x;
    float* Ks = kred;   // alias during QK phase

    {   // stage one K row + one V row per thread with circular d-shift
        int m = tid, sh = m >> 4;
        const float4* kr4 = (const float4*)(Kp + (size_t)m*Ee);
        const float4* vr4 = (const float4*)(Vp + (size_t)m*Ee);
        #pragma unroll
        for (int j4 = 0; j4 < 4; j4++){
            float4 kv = kr4[j4], vv = vr4[j4];
            Ks[m*17 + ((j4*4+0+sh)&15)] = kv.x;
            Ks[m*17 + ((j4*4+1+sh)&15)] = kv.y;
            Ks[m*17 + ((j4*4+2+sh)&15)] = kv.z;
            Ks[m*17 + ((j4*4+3+sh)&15)] = kv.w;
            Vs[m][(j4*4+0+sh)&15] = vv.x;
            Vs[m][(j4*4+1+sh)&15] = vv.y;
            Vs[m][(j4*4+2+sh)&15] = vv.z;
            Vs[m][(j4*4+3+sh)&15] = vv.w;
        }
        int r = tid >> 3, dq = (tid & 7)*2;
        float2 q2 = *(const float2*)(Qp + (size_t)r*Ee + dq);
        qs[r][dq]   = q2.x*0.25f;      // fold 1/sqrt(D)
        qs[r][dq+1] = q2.y*0.25f;
    }
    __syncthreads();

    int n2 = tid >> 4, s16 = tid & 15;
    int m0 = s16*16;

    float q0[16], q1[16];
    #pragma unroll
    for (int d = 0; d < 16; d++){ q0[d] = qs[n2][d]; q1[d] = qs[n2+16][d]; }

    // scores: edge bias + QK^T
    float acc0[16], acc1[16];
    {
        const float* sr0 = Sc + ((size_t)b*Nn + rg*32 + n2)*Nn + m0;
        const float* sr1 = sr0 + (size_t)16*Nn;
        #pragma unroll
        for (int j = 0; j < 16; j += 4){
            float4 v0 = *(const float4*)&sr0[j];
            acc0[j]   = fmaf(v0.x, al, be); acc0[j+1] = fmaf(v0.y, al, be);
            acc0[j+2] = fmaf(v0.z, al, be); acc0[j+3] = fmaf(v0.w, al, be);
            float4 v1 = *(const float4*)&sr1[j];
            acc1[j]   = fmaf(v1.x, al, be); acc1[j+1] = fmaf(v1.y, al, be);
            acc1[j+2] = fmaf(v1.z, al, be); acc1[j+3] = fmaf(v1.w, al, be);
        }
    }
    #pragma unroll
    for (int j = 0; j < 16; j++){
        const float* kr = &Ks[(m0+j)*17];
        float a0 = acc0[j], a1 = acc1[j];
        #pragma unroll
        for (int d = 0; d < 16; d++){
            float kv = kr[(d+s16)&15];
            a0 = fmaf(q0[d], kv, a0);
            a1 = fmaf(q1[d], kv, a1);
        }
        acc0[j] = a0; acc1[j] = a1;
    }

    // softmax over full rows (reduce across 16 s16-lanes; xor<16 stays in half-warp)
    float mx0 = -1e30f, mx1 = -1e30f;
    #pragma unroll
    for (int j = 0; j < 16; j++){ mx0 = fmaxf(mx0, acc0[j]); mx1 = fmaxf(mx1, acc1[j]); }
    #pragma unroll
    for (int o = 1; o < 16; o <<= 1){
        mx0 = fmaxf(mx0, __shfl_xor_sync(0xffffffffu, mx0, o));
        mx1 = fmaxf(mx1, __shfl_xor_sync(0xffffffffu, mx1, o));
    }
    float sm0 = 0.f, sm1 = 0.f;
    #pragma unroll
    for (int j = 0; j < 16; j++){
        acc0[j] = __expf(acc0[j]-mx0); sm0 += acc0[j];
        acc1[j] = __expf(acc1[j]-mx1); sm1 += acc1[j];
    }
    #pragma unroll
    for (int o = 1; o < 16; o <<= 1){
        sm0 += __shfl_xor_sync(0xffffffffu, sm0, o);
        sm1 += __shfl_xor_sync(0xffffffffu, sm1, o);
    }
    if (s16 == 0){ sminv[n2] = 1.f/sm0; sminv[n2+16] = 1.f/sm1; }

    // PV partials over this thread's m-segment
    float p0[16], p1[16];
    #pragma unroll
    for (int d = 0; d < 16; d++){ p0[d] = 0.f; p1[d] = 0.f; }
    #pragma unroll
    for (int j = 0; j < 16; j++){
        const float* vr = &Vs[m0+j][0];
        float e0 = acc0[j], e1 = acc1[j];
        #pragma unroll
        for (int d = 0; d < 16; d++){
            float vv = vr[(d+s16)&15];
            p0[d] = fmaf(e0, vv, p0[d]);
            p1[d] = fmaf(e1, vv, p1[d]);
        }
    }
    // fold s16 and s16+8 via shfl (halves red footprint)
    #pragma unroll
    for (int d = 0; d < 16; d++){
        p0[d] += __shfl_xor_sync(0xffffffffu, p0[d], 8);
        p1[d] += __shfl_xor_sync(0xffffffffu, p1[d], 8);
    }
    __syncthreads();                // all Ks reads done; safe to overwrite kred
    float* red = kred;              // [8][545]
    if (s16 < 8){
        #pragma unroll
        for (int d = 0; d < 16; d++){
            red[s16*545 + n2*17 + d]      = p0[d];
            red[s16*545 + (n2+16)*17 + d] = p1[d];
        }
    }
    __syncthreads();

    // final reduce + scale + bf16 split out; thread -> (row r, d-pair)
    {
        int r = tid >> 3, dp = (tid & 7)*2;
        float s0 = 0.f, s1 = 0.f;
        #pragma unroll
        for (int s = 0; s < 8; s++){
            s0 += red[s*545 + r*17 + dp];
            s1 += red[s*545 + r*17 + dp + 1];
        }
        float iv = sminv[r];
        float v0 = s0*iv, v1 = s1*iv;
        size_t off = base + (size_t)(rg*32 + r)*Ee + h*16 + dp;
        __nv_bfloat16 h0 = __float2bfloat16(v0), h1 = __float2bfloat16(v1);
        __nv_bfloat162 hp; hp.x = h0; hp.y = h1;
        __nv_bfloat162 lp;
        lp.x = __float2bfloat16(v0 - __bfloat162float(h0));
        lp.y = __float2bfloat16(v1 - __bfloat162float(h1));
        *(__nv_bfloat162*)&Oh[off] = hp;
        *(__nv_bfloat162*)&Ol[off] = lp;
    }
}

// instance norm + bf16 split output
__global__ void k_inorm(const float* __restrict__ X, float* __restrict__ Y,
                        const float* __restrict__ wbase, const float* __restrict__ bbase,
                        __nv_bfloat16* __restrict__ Yh, __nv_bfloat16* __restrict__ Yl)
{
    int z = blockIdx.z, b = blockIdx.x, e0 = blockIdx.y*64;
    const float* w = wbase + (size_t)z*Ee;
    const float* bp = bbase + (size_t)z*Ee;
    int tid = threadIdx.x;
    int el = tid & 63, nc = tid >> 6;
    size_t base = ((size_t)(z*Bb+b))*Nn*Ee;
    float s = 0.f, ss = 0.f;
    for (int n = nc; n < Nn; n += 4){
        float v = X[base + (size_t)n*Ee + e0 + el];
        s += v; ss += v*v;
    }
    __shared__ float sh_s[4][64], sh_ss[4][64];
    __shared__ float muA[64], invA[64];
    sh_s[nc][el] = s; sh_ss[nc][el] = ss;
    __syncthreads();
    if (nc == 0){
        float S  = sh_s[0][el]+sh_s[1][el]+sh_s[2][el]+sh_s[3][el];
        float SS = sh_ss[0][el]+sh_ss[1][el]+sh_ss[2][el]+sh_ss[3][el];
        float mu = S*(1.f/Nn);
        float var = SS*(1.f/Nn) - mu*mu;
        muA[el] = mu;
        invA[el] = rsqrtf(var + 1e-5f);
    }
    __syncthreads();
    float mu = muA[el];
    float sc = invA[el]*w[e0+el];
    float sb = bp[e0+el];
    for (int n = nc; n < Nn; n += 4){
        size_t off = base + (size_t)n*Ee + e0 + el;
        float y = (X[off]-mu)*sc + sb;
        Y[off] = y;
        __nv_bfloat16 hi = __float2bfloat16(y);
        Yh[off] = hi;
        Yl[off] = __float2bfloat16(y - __bfloat162float(hi));
    }
}

__global__ void k_copy(float* __restrict__ dst, const float* __restrict__ src, int n)
{
    int i = blockIdx.x*256 + threadIdx.x;
    if (i < n) dst[i] = src[i];
}

// ================= host launcher =================
extern "C" void kernel_launch(void* const* d_in, const int* in_sizes, int n_in,
                              void* d_out, int out_size)
{
    const float* data      = (const float*)d_in[0];
    const float* node_rand = (const float*)d_in[1];
    const float* Wnode = (const float*)d_in[2];
    const float* bnode = (const float*)d_in[3];
    const float* Wedge = (const float*)d_in[4];
    const float* bedge = (const float*)d_in[5];
    const float* Wq    = (const float*)d_in[6];
    const float* Wk    = (const float*)d_in[7];
    const float* Wv    = (const float*)d_in[8];
    const float* Wcomb = (const float*)d_in[9];
    const float* bcomb = (const float*)d_in[10];
    const float* n1w   = (const float*)d_in[11];
    const float* n1b   = (const float*)d_in[12];
    const float* W1    = (const float*)d_in[13];
    const float* b1    = (const float*)d_in[14];
    const float* W2    = (const float*)d_in[15];
    const float* b2    = (const float*)d_in[16];
    const float* n2w   = (const float*)d_in[17];
    const float* n2b   = (const float*)d_in[18];
    const float* Wmix  = (const float*)d_in[19];

    float *scaled, *scaledT, *mn, *mx, *alpha, *beta;
    float *bufA, *bufB, *Qb, *Kb, *Vb, *t1, *o1;
    __nv_bfloat16 *xhA,*xlA,*xhB,*xlB,*oh,*ol,*o1h,*o1l,*ffh,*ffl;
    __nv_bfloat16 *wqh,*wql,*wkh,*wkl,*wvh,*wvl,*wch,*wcl,*w1h,*w1l,*w2h,*w2l;
    cudaGetSymbolAddress((void**)&scaled,  g_scaled);
    cudaGetSymbolAddress((void**)&scaledT, g_scaledT);
    cudaGetSymbolAddress((void**)&mn,      g_mn);
    cudaGetSymbolAddress((void**)&mx,      g_mx);
    cudaGetSymbolAddress((void**)&alpha,   g_alpha);
    cudaGetSymbolAddress((void**)&beta,    g_beta);
    cudaGetSymbolAddress((void**)&bufA,    g_bufA);
    cudaGetSymbolAddress((void**)&bufB,    g_bufB);
    cudaGetSymbolAddress((void**)&Qb,      g_Q);
    cudaGetSymbolAddress((void**)&Kb,      g_K);
    cudaGetSymbolAddress((void**)&Vb,      g_V);
    cudaGetSymbolAddress((void**)&t1,      g_t1);
    cudaGetSymbolAddress((void**)&o1,      g_o1);
    cudaGetSymbolAddress((void**)&xhA, g_xhA); cudaGetSymbolAddress((void**)&xlA, g_xlA);
    cudaGetSymbolAddress((void**)&xhB, g_xhB); cudaGetSymbolAddress((void**)&xlB, g_xlB);
    cudaGetSymbolAddress((void**)&oh,  g_oh);  cudaGetSymbolAddress((void**)&ol,  g_ol);
    cudaGetSymbolAddress((void**)&o1h, g_o1h); cudaGetSymbolAddress((void**)&o1l, g_o1l);
    cudaGetSymbolAddress((void**)&ffh, g_ffh); cudaGetSymbolAddress((void**)&ffl, g_ffl);
    cudaGetSymbolAddress((void**)&wqh, g_wqh); cudaGetSymbolAddress((void**)&wql, g_wql);
    cudaGetSymbolAddress((void**)&wkh, g_wkh); cudaGetSymbolAddress((void**)&wkl, g_wkl);
    cudaGetSymbolAddress((void**)&wvh, g_wvh); cudaGetSymbolAddress((void**)&wvl, g_wvl);
    cudaGetSymbolAddress((void**)&wch, g_wch); cudaGetSymbolAddress((void**)&wcl, g_wcl);
    cudaGetSymbolAddress((void**)&w1h, g_w1h); cudaGetSymbolAddress((void**)&w1l, g_w1l);
    cudaGetSymbolAddress((void**)&w2h, g_w2h); cudaGetSymbolAddress((void**)&w2l, g_w2l);

    // setup
    k_minmax<<<Bb, 256>>>(data, mn, mx);
    k_scale<<<dim3(8,8,Bb), dim3(32,8)>>>(data, mn, mx, scaled, scaledT);
    k_ab<<<dim3(Ll*2, Hh), 32>>>(Wedge, bedge, Wmix, alpha, beta);
    k_emb<<<BNE/256, 256>>>(node_rand, Wnode, bnode, bufA, xhA, xlA);
    k_tsplit<<<dim3(8,8,10),  dim3(32,8)>>>(Wq,    wqh, wql, 256, 256);
    k_tsplit<<<dim3(8,8,10),  dim3(32,8)>>>(Wk,    wkh, wkl, 256, 256);
    k_tsplit<<<dim3(8,8,10),  dim3(32,8)>>>(Wv,    wvh, wvl, 256, 256);
    k_tsplit<<<dim3(8,8,10),  dim3(32,8)>>>(Wcomb, wch, wcl, 256, 256);
    k_tsplit<<<dim3(16,8,10), dim3(32,8)>>>(W1,    w1h, w1l, 256, 512);
    k_tsplit<<<dim3(8,16,10), dim3(32,8)>>>(W2,    w2h, w2l, 512, 256);

    for (int i = 0; i < Ll; i++){
        float* Xc = (i & 1) ? bufB : bufA;
        __nv_bfloat16* xhc = (i & 1) ? xhB : xhA;
        __nv_bfloat16* xlc = (i & 1) ? xlB : xlA;
        __nv_bfloat16* xhn = (i & 1) ? xhA : xhB;
        __nv_bfloat16* xln = (i & 1) ? xlA : xlB;
        float* Xn = (i & 1) ? bufA : bufB;
        size_t w256 = (size_t)i*2*65536;
        size_t w512 = (size_t)i*2*131072;
        const float* bcomb_i = bcomb + (size_t)i*2*Ee;
        const float* b1_i    = b1    + (size_t)i*2*FFh;
        const float* b2_i    = b2    + (size_t)i*2*Ee;

        k_tqkv<<<dim3(12,16,2), 128>>>(xhc, xlc,
            wqh + w256, wql + w256, wkh + w256, wkl + w256, wvh + w256, wvl + w256,
            Qb, Kb, Vb);
        k_attn<<<dim3(8, Bb*Hh, 2), 256>>>(Qb, Kb, Vb, scaled, scaledT,
            alpha + i*2*Hh, beta + i*2*Hh, oh, ol);
        k_tgemm<<<dim3(4,16,2), 128>>>(oh, ol, BNE, wch + w256, wcl + w256, 65536,
            bcomb_i, Ee, Xc, BNE, t1, nullptr, nullptr, BNE, 256, 256, 0);
        k_inorm<<<dim3(Bb,4,2), 256>>>(t1, o1, n1w + (size_t)i*2*Ee, n1b + (size_t)i*2*Ee, o1h, o1l);
        k_tgemm<<<dim3(8,16,2), 128>>>(o1h, o1l, BNE, w1h + w512, w1l + w512, 131072,
            b1_i, FFh, nullptr, 0, nullptr, ffh, ffl, BNF, 512, 256, 1);
        k_tgemm<<<dim3(4,16,2), 128>>>(ffh, ffl, BNF, w2h + w512, w2l + w512, 131072,
            b2_i, Ee, o1, BNE, t1, nullptr, nullptr, BNE, 256, 512, 0);
        k_inorm<<<dim3(Bb,4,2), 256>>>(t1, Xn, n2w + (size_t)i*2*Ee, n2b + (size_t)i*2*Ee, xhn, xln);
    }

    int total = 2*BNE;
    if (out_size < total) total = out_size;
    k_copy<<<(total+255)/256, 256>>>((float*)d_out, bufB, total);
}

// round 9
// speedup vs baseline: 2.3638x; 1.1802x over previous
#include <cuda_runtime.h>
#include <cuda_bf16.h>
#include <cstdint>

#define Bb 4
#define Nn 256
#define Ee 256
#define Hh 16
#define Dd 16
#define FFh 512
#define Ll 5
#define BNE (Bb*Nn*Ee)          // 262144
#define BNF (Bb*Nn*FFh)         // 524288

// ================= device scratch =================
__device__ float g_scaled [Bb*Nn*Nn];
__device__ float g_scaledT[Bb*Nn*Nn];
__device__ float g_mn[Bb], g_mx[Bb];
__device__ float g_alpha[Ll*2*Hh], g_beta[Ll*2*Hh];
__device__ float g_bufA[2*BNE], g_bufB[2*BNE];
__device__ float g_Q[2*BNE], g_K[2*BNE], g_V[2*BNE];
__device__ float g_t1[2*BNE], g_o1[2*BNE];

// bf16 split activations
__device__ __nv_bfloat16 g_xhA[2*BNE], g_xlA[2*BNE], g_xhB[2*BNE], g_xlB[2*BNE];
__device__ __nv_bfloat16 g_oh[2*BNE],  g_ol[2*BNE];
__device__ __nv_bfloat16 g_o1h[2*BNE], g_o1l[2*BNE];
__device__ __nv_bfloat16 g_ffh[2*BNF], g_ffl[2*BNF];
// bf16 split transposed weights (WT[N,K])
__device__ __nv_bfloat16 g_wqh[10*65536],  g_wql[10*65536];
__device__ __nv_bfloat16 g_wkh[10*65536],  g_wkl[10*65536];
__device__ __nv_bfloat16 g_wvh[10*65536],  g_wvl[10*65536];
__device__ __nv_bfloat16 g_wch[10*65536],  g_wcl[10*65536];
__device__ __nv_bfloat16 g_w1h[10*131072], g_w1l[10*131072];
__device__ __nv_bfloat16 g_w2h[10*131072], g_w2l[10*131072];

// ================= small kernels =================
__global__ void k_minmax(const float* __restrict__ data, float* mn, float* mx)
{
    int b = blockIdx.x, tid = threadIdx.x;
    const float* p = data + (size_t)b*Nn*Nn;
    float lmn = 1e30f, lmx = -1e30f;
    for (int i = tid; i < Nn*Nn; i += 256) { float v = p[i]; lmn = fminf(lmn,v); lmx = fmaxf(lmx,v); }
    __shared__ float smn[256], smx[256];
    smn[tid]=lmn; smx[tid]=lmx; __syncthreads();
    for (int s=128; s; s>>=1){ if (tid<s){ smn[tid]=fminf(smn[tid],smn[tid+s]); smx[tid]=fmaxf(smx[tid],smx[tid+s]); } __syncthreads(); }
    if (!tid){ mn[b]=smn[0]; mx[b]=smx[0]; }
}

__global__ void k_scale(const float* __restrict__ data, const float* __restrict__ mn,
                        const float* __restrict__ mx, float* __restrict__ S, float* __restrict__ ST)
{
    int b = blockIdx.z;
    float m0v = mn[b], r = mx[b]-m0v; if (r == 0.f) r = 1.f;
    float inv = 1.f/r;
    __shared__ float tile[32][33];
    int n0 = blockIdx.y*32, mm0 = blockIdx.x*32;
    int tx = threadIdx.x, ty0 = threadIdx.y;
    #pragma unroll
    for (int i=0;i<4;i++){
        int ty = ty0 + i*8;
        float v = (data[((size_t)b*Nn + n0+ty)*Nn + mm0+tx] - m0v)*inv;
        S[((size_t)b*Nn + n0+ty)*Nn + mm0+tx] = v;
        tile[ty][tx] = v;
    }
    __syncthreads();
    #pragma unroll
    for (int i=0;i<4;i++){
        int ty = ty0 + i*8;
        ST[((size_t)b*Nn + mm0+ty)*Nn + n0+tx] = tile[tx][ty];
    }
}

__global__ void k_ab(const float* __restrict__ Wedge, const float* __restrict__ bedge,
                     const float* __restrict__ Wmix, float* __restrict__ alpha, float* __restrict__ beta)
{
    int ij = blockIdx.x, h = blockIdx.y, lane = threadIdx.x;
    float a = 0.f, bb = 0.f;
    for (int e = lane; e < Ee; e += 32){
        float wm = Wmix[((size_t)ij*Ee + e)*Hh + h];
        a  += Wedge[e]*wm;
        bb += bedge[e]*wm;
    }
    for (int o=16;o;o>>=1){ a += __shfl_xor_sync(0xffffffffu,a,o); bb += __shfl_xor_sync(0xffffffffu,bb,o); }
    if (!lane){ alpha[ij*Hh+h]=a; beta[ij*Hh+h]=bb; }
}

__global__ void k_emb(const float* __restrict__ nr, const float* __restrict__ Wn,
                      const float* __restrict__ bn, float* __restrict__ X,
                      __nv_bfloat16* __restrict__ xh, __nv_bfloat16* __restrict__ xl)
{
    int idx = blockIdx.x*256 + threadIdx.x;
    int e = idx & (Ee-1), bni = idx >> 8;
    float v = nr[bni]*Wn[e] + bn[e];
    X[idx] = v; X[idx + BNE] = v;
    __nv_bfloat16 hi = __float2bfloat16(v);
    __nv_bfloat16 lo = __float2bfloat16(v - __bfloat162float(hi));
    xh[idx]=hi; xh[idx+BNE]=hi;
    xl[idx]=lo; xl[idx+BNE]=lo;
}

// merged transpose + split for all 6 weight families, one launch (5120 blocks)
__global__ void k_tsplit_all(
    const float* __restrict__ Wq, const float* __restrict__ Wk,
    const float* __restrict__ Wv, const float* __restrict__ Wc,
    const float* __restrict__ W1, const float* __restrict__ W2,
    __nv_bfloat16* wqh, __nv_bfloat16* wql,
    __nv_bfloat16* wkh, __nv_bfloat16* wkl,
    __nv_bfloat16* wvh, __nv_bfloat16* wvl,
    __nv_bfloat16* wch, __nv_bfloat16* wcl,
    __nv_bfloat16* w1h, __nv_bfloat16* w1l,
    __nv_bfloat16* w2h, __nv_bfloat16* w2l)
{
    int bid = blockIdx.x;
    const float* s; __nv_bfloat16 *oh, *ol;
    int K, N, n0, k0, mat;
    if (bid < 2560){
        int type = bid / 640, loc = bid - type*640;
        mat = loc >> 6; int tile = loc & 63;
        K = 256; N = 256;
        n0 = (tile & 7)*32; k0 = (tile >> 3)*32;
        s  = (type==0?Wq:type==1?Wk:type==2?Wv:Wc);
        oh = (type==0?wqh:type==1?wkh:type==2?wvh:wch);
        ol = (type==0?wql:type==1?wkl:type==2?wvl:wcl);
    } else if (bid < 3840){
        int loc = bid - 2560;
        mat = loc >> 7; int tile = loc & 127;
        K = 256; N = 512;
        n0 = (tile & 15)*32; k0 = (tile >> 4)*32;
        s = W1; oh = w1h; ol = w1l;
    } else {
        int loc = bid - 3840;
        mat = loc >> 7; int tile = loc & 127;
        K = 512; N = 256;
        n0 = (tile & 7)*32; k0 = (tile >> 3)*32;
        s = W2; oh = w2h; ol = w2l;
    }
    s  += (size_t)mat*K*N;
    oh += (size_t)mat*K*N;
    ol += (size_t)mat*K*N;
    __shared__ float ts[32][33];
    int tx = threadIdx.x, ty = threadIdx.y;
    #pragma unroll
    for (int i=0;i<4;i++) ts[ty+i*8][tx] = s[(size_t)(k0+ty+i*8)*N + n0+tx];
    __syncthreads();
    #pragma unroll
    for (int i=0;i<4;i++){
        int n = n0+ty+i*8, k = k0+tx;
        float v = ts[tx][ty+i*8];
        __nv_bfloat16 hi = __float2bfloat16(v);
        oh[(size_t)n*K + k] = hi;
        ol[(size_t)n*K + k] = __float2bfloat16(v - __bfloat162float(hi));
    }
}

// ================= HMMA 3xBF16 GEMM core, cp.async double-buffered =================
__device__ __forceinline__ void cp16(uint32_t dst, const void* src){
    asm volatile("cp.async.cg.shared.global [%0], [%1], 16;\n" :: "r"(dst), "l"(src));
}

__device__ __forceinline__ void hmma(float* c, const uint32_t* a, const uint32_t* b){
    asm volatile("mma.sync.aligned.m16n8k16.row.col.f32.bf16.bf16.f32 "
        "{%0,%1,%2,%3}, {%4,%5,%6,%7}, {%8,%9}, {%0,%1,%2,%3};"
        : "+f"(c[0]), "+f"(c[1]), "+f"(c[2]), "+f"(c[3])
        : "r"(a[0]), "r"(a[1]), "r"(a[2]), "r"(a[3]), "r"(b[0]), "r"(b[1]));
}

// C[64,64] at (m0,n0): C = A@W; A from (ah+al)[M,K], W via WT[N,K]=(wh+wl)
// 128 threads / 4 warps; warp tile 32x32; smem rows 40 bf16 (80B), data cols 0..31
__device__ __forceinline__ void tgemm_core(
    const __nv_bfloat16* __restrict__ ah, const __nv_bfloat16* __restrict__ al,
    const __nv_bfloat16* __restrict__ wh, const __nv_bfloat16* __restrict__ wl,
    const float* __restrict__ bias, const float* __restrict__ res,
    float* __restrict__ Cf, __nv_bfloat16* __restrict__ Chi, __nv_bfloat16* __restrict__ Clo,
    int m0, int n0, int Ng, int K, int relu)
{
    __shared__ __align__(16) __nv_bfloat16 smb[2][4][64*40];  // [stage][Ah,Al,Bh,Bl]
    int tid = threadIdx.x;
    int lane = tid & 31, w = tid >> 5;
    int wm = (w >> 1)*32, wn = (w & 1)*32;
    int g = lane >> 2, tg = lane & 3;
    uint32_t sbase;
    asm("{ .reg .u64 t; cvta.to.shared.u64 t, %1; cvt.u32.u64 %0, t; }"
        : "=r"(sbase) : "l"((void*)&smb[0][0][0]));

    float acc[2][4][4];
    #pragma unroll
    for (int mi=0;mi<2;mi++)
        #pragma unroll
        for (int ni=0;ni<4;ni++)
            #pragma unroll
            for (int q=0;q<4;q++) acc[mi][ni][q]=0.f;

    const int nch = K >> 5;
    int crow = tid >> 2, cseg = (tid & 3)*8;   // 32 rows x 4 segs; 2 its -> 64 rows

    auto issue = [&](int c){
        uint32_t sb2 = sbase + (uint32_t)((c & 1) ? 20480 : 0);
        int co = c*32 + cseg;
        #pragma unroll
        for (int it = 0; it < 2; it++){
            int row = crow + it*32;
            uint32_t dof = (uint32_t)((row*40 + cseg)*2);
            cp16(sb2         + dof, ah + (size_t)(m0+row)*K + co);
            cp16(sb2 + 5120  + dof, al + (size_t)(m0+row)*K + co);
            cp16(sb2 + 10240 + dof, wh + (size_t)(n0+row)*K + co);
            cp16(sb2 + 15360 + dof, wl + (size_t)(n0+row)*K + co);
        }
        asm volatile("cp.async.commit_group;\n");
    };

    issue(0);
    for (int c = 0; c < nch; c++){
        asm volatile("cp.async.wait_group 0;\n");
        __syncthreads();
        if (c + 1 < nch) issue(c + 1);
        int st = c & 1;
        const __nv_bfloat16* pA0 = &smb[st][0][0];
        const __nv_bfloat16* pA1 = &smb[st][1][0];
        const __nv_bfloat16* pB0 = &smb[st][2][0];
        const __nv_bfloat16* pB1 = &smb[st][3][0];
        #pragma unroll
        for (int ks = 0; ks < 2; ks++){
            int kb = ks*16 + 2*tg;
            uint32_t fah[2][4], fal[2][4];
            #pragma unroll
            for (int mi = 0; mi < 2; mi++){
                int rb = wm + mi*16 + g;
                fah[mi][0] = *(const uint32_t*)&pA0[rb*40 + kb];
                fah[mi][1] = *(const uint32_t*)&pA0[(rb+8)*40 + kb];
                fah[mi][2] = *(const uint32_t*)&pA0[rb*40 + kb + 8];
                fah[mi][3] = *(const uint32_t*)&pA0[(rb+8)*40 + kb + 8];
                fal[mi][0] = *(const uint32_t*)&pA1[rb*40 + kb];
                fal[mi][1] = *(const uint32_t*)&pA1[(rb+8)*40 + kb];
                fal[mi][2] = *(const uint32_t*)&pA1[rb*40 + kb + 8];
                fal[mi][3] = *(const uint32_t*)&pA1[(rb+8)*40 + kb + 8];
            }
            uint32_t fbh[4][2], fbl[4][2];
            #pragma unroll
            for (int ni = 0; ni < 4; ni++){
                int nb = wn + ni*8 + g;
                fbh[ni][0] = *(const uint32_t*)&pB0[nb*40 + kb];
                fbh[ni][1] = *(const uint32_t*)&pB0[nb*40 + kb + 8];
                fbl[ni][0] = *(const uint32_t*)&pB1[nb*40 + kb];
                fbl[ni][1] = *(const uint32_t*)&pB1[nb*40 + kb + 8];
            }
            #pragma unroll
            for (int mi = 0; mi < 2; mi++)
                #pragma unroll
                for (int ni = 0; ni < 4; ni++){
                    hmma(acc[mi][ni], fah[mi], fbh[ni]);
                    hmma(acc[mi][ni], fah[mi], fbl[ni]);
                    hmma(acc[mi][ni], fal[mi], fbh[ni]);
                }
        }
    }

    #pragma unroll
    for (int mi = 0; mi < 2; mi++){
        #pragma unroll
        for (int ni = 0; ni < 4; ni++){
            int col = n0 + wn + ni*8 + 2*tg;
            float b0 = bias ? bias[col]   : 0.f;
            float b1 = bias ? bias[col+1] : 0.f;
            #pragma unroll
            for (int half = 0; half < 2; half++){
                int m = m0 + wm + mi*16 + g + half*8;
                float v0 = acc[mi][ni][half*2+0] + b0;
                float v1 = acc[mi][ni][half*2+1] + b1;
                if (res){
                    v0 += res[(size_t)m*Ng + col];
                    v1 += res[(size_t)m*Ng + col+1];
                }
                if (relu){ v0 = fmaxf(v0, 0.f); v1 = fmaxf(v1, 0.f); }
                if (Cf){
                    float2 o; o.x = v0; o.y = v1;
                    *(float2*)&Cf[(size_t)m*Ng + col] = o;
                }
                if (Chi){
                    __nv_bfloat16 h0 = __float2bfloat16(v0), h1 = __float2bfloat16(v1);
                    __nv_bfloat162 hp; hp.x = h0; hp.y = h1;
                    __nv_bfloat162 lp;
                    lp.x = __float2bfloat16(v0 - __bfloat162float(h0));
                    lp.y = __float2bfloat16(v1 - __bfloat162float(h1));
                    *(__nv_bfloat162*)&Chi[(size_t)m*Ng + col] = hp;
                    *(__nv_bfloat162*)&Clo[(size_t)m*Ng + col] = lp;
                }
            }
        }
    }
}

// fused QKV: grid (12, 16, 2): wsel = x>>2 (0=Q,1=K,2=V), nt = x&3
__global__ void __launch_bounds__(128) k_tqkv(
                       const __nv_bfloat16* __restrict__ xh, const __nv_bfloat16* __restrict__ xl,
                       const __nv_bfloat16* wqh, const __nv_bfloat16* wql,
                       const __nv_bfloat16* wkh, const __nv_bfloat16* wkl,
                       const __nv_bfloat16* wvh, const __nv_bfloat16* wvl,
                       float* Q, float* K, float* V)
{
    int wsel = blockIdx.x >> 2, nt = blockIdx.x & 3, z = blockIdx.z;
    int az = wsel ? (1 - z) : z;
    const __nv_bfloat16 *wh, *wl; float* out;
    if (wsel == 0){ wh = wqh; wl = wql; out = Q; }
    else if (wsel == 1){ wh = wkh; wl = wkl; out = K; }
    else { wh = wvh; wl = wvl; out = V; }
    tgemm_core(xh + (size_t)az*BNE, xl + (size_t)az*BNE,
               wh + (size_t)z*65536, wl + (size_t)z*65536,
               nullptr, nullptr,
               out + (size_t)z*BNE, nullptr, nullptr,
               blockIdx.y*64, nt*64, 256, 256, 0);
}

// generic: grid (Ng/64, 16, 2)
__global__ void __launch_bounds__(128) k_tgemm(
                        const __nv_bfloat16* __restrict__ ah, const __nv_bfloat16* __restrict__ al, int aStrideZ,
                        const __nv_bfloat16* __restrict__ wh, const __nv_bfloat16* __restrict__ wl, int wStrideZ,
                        const float* bias, int biasStrideZ,
                        const float* res, int resStrideZ,
                        float* Cf, __nv_bfloat16* Chi, __nv_bfloat16* Clo, int cStrideZ,
                        int Ng, int K, int relu)
{
    int z = blockIdx.z;
    tgemm_core(ah + (size_t)z*aStrideZ, al + (size_t)z*aStrideZ,
               wh + (size_t)z*wStrideZ, wl + (size_t)z*wStrideZ,
               bias ? bias + (size_t)z*biasStrideZ : nullptr,
               res  ? res  + (size_t)z*resStrideZ  : nullptr,
               Cf  ? Cf  + (size_t)z*cStrideZ : nullptr,
               Chi ? Chi + (size_t)z*cStrideZ : nullptr,
               Clo ? Clo + (size_t)z*cStrideZ : nullptr,
               blockIdx.y*64, blockIdx.x*64, Ng, K, relu);
}

// ================= fused attention: score + bias + softmax + PV =================
__global__ void __launch_bounds__(256) k_attn(
    const float* __restrict__ Q, const float* __restrict__ Kg, const float* __restrict__ Vg,
    const float* __restrict__ scaled, const float* __restrict__ scaledT,
    const float* __restrict__ alpha, const float* __restrict__ beta,
    __nv_bfloat16* __restrict__ Oh, __nv_bfloat16* __restrict__ Ol)
{
    __shared__ float qs[32][17];
    __shared__ float Vs[256][17];
    __shared__ float kred[8*545];   // Ks[256][17], later red[8][545]
    __shared__ float sminv[32];

    int rg = blockIdx.x, bh = blockIdx.y, z = blockIdx.z;
    int b = bh >> 4, h = bh & 15;
    const float* Sc = z ? scaledT : scaled;
    size_t base = ((size_t)(z*Bb+b))*(size_t)Nn*Ee;
    const float* Kp = Kg + base + h*16;
    const float* Vp = Vg + base + h*16;
    const float* Qp = Q  + base + (size_t)rg*32*Ee + h*16;
    float al = alpha[z*Hh+h], be = beta[z*Hh+h];
    int tid = threadIdx.x;
    float* Ks = kred;

    {
        int m = tid, sh = m >> 4;
        const float4* kr4 = (const float4*)(Kp + (size_t)m*Ee);
        const float4* vr4 = (const float4*)(Vp + (size_t)m*Ee);
        #pragma unroll
        for (int j4 = 0; j4 < 4; j4++){
            float4 kv = kr4[j4], vv = vr4[j4];
            Ks[m*17 + ((j4*4+0+sh)&15)] = kv.x;
            Ks[m*17 + ((j4*4+1+sh)&15)] = kv.y;
            Ks[m*17 + ((j4*4+2+sh)&15)] = kv.z;
            Ks[m*17 + ((j4*4+3+sh)&15)] = kv.w;
            Vs[m][(j4*4+0+sh)&15] = vv.x;
            Vs[m][(j4*4+1+sh)&15] = vv.y;
            Vs[m][(j4*4+2+sh)&15] = vv.z;
            Vs[m][(j4*4+3+sh)&15] = vv.w;
        }
        int r = tid >> 3, dq = (tid & 7)*2;
        float2 q2 = *(const float2*)(Qp + (size_t)r*Ee + dq);
        qs[r][dq]   = q2.x*0.25f;
        qs[r][dq+1] = q2.y*0.25f;
    }
    __syncthreads();

    int n2 = tid >> 4, s16 = tid & 15;
    int m0 = s16*16;

    float q0[16], q1[16];
    #pragma unroll
    for (int d = 0; d < 16; d++){ q0[d] = qs[n2][d]; q1[d] = qs[n2+16][d]; }

    float acc0[16], acc1[16];
    {
        const float* sr0 = Sc + ((size_t)b*Nn + rg*32 + n2)*Nn + m0;
        const float* sr1 = sr0 + (size_t)16*Nn;
        #pragma unroll
        for (int j = 0; j < 16; j += 4){
            float4 v0 = *(const float4*)&sr0[j];
            acc0[j]   = fmaf(v0.x, al, be); acc0[j+1] = fmaf(v0.y, al, be);
            acc0[j+2] = fmaf(v0.z, al, be); acc0[j+3] = fmaf(v0.w, al, be);
            float4 v1 = *(const float4*)&sr1[j];
            acc1[j]   = fmaf(v1.x, al, be); acc1[j+1] = fmaf(v1.y, al, be);
            acc1[j+2] = fmaf(v1.z, al, be); acc1[j+3] = fmaf(v1.w, al, be);
        }
    }
    #pragma unroll
    for (int j = 0; j < 16; j++){
        const float* kr = &Ks[(m0+j)*17];
        float a0 = acc0[j], a1 = acc1[j];
        #pragma unroll
        for (int d = 0; d < 16; d++){
            float kv = kr[(d+s16)&15];
            a0 = fmaf(q0[d], kv, a0);
            a1 = fmaf(q1[d], kv, a1);
        }
        acc0[j] = a0; acc1[j] = a1;
    }

    float mx0 = -1e30f, mx1 = -1e30f;
    #pragma unroll
    for (int j = 0; j < 16; j++){ mx0 = fmaxf(mx0, acc0[j]); mx1 = fmaxf(mx1, acc1[j]); }
    #pragma unroll
    for (int o = 1; o < 16; o <<= 1){
        mx0 = fmaxf(mx0, __shfl_xor_sync(0xffffffffu, mx0, o));
        mx1 = fmaxf(mx1, __shfl_xor_sync(0xffffffffu, mx1, o));
    }
    float sm0 = 0.f, sm1 = 0.f;
    #pragma unroll
    for (int j = 0; j < 16; j++){
        acc0[j] = __expf(acc0[j]-mx0); sm0 += acc0[j];
        acc1[j] = __expf(acc1[j]-mx1); sm1 += acc1[j];
    }
    #pragma unroll
    for (int o = 1; o < 16; o <<= 1){
        sm0 += __shfl_xor_sync(0xffffffffu, sm0, o);
        sm1 += __shfl_xor_sync(0xffffffffu, sm1, o);
    }
    if (s16 == 0){ sminv[n2] = 1.f/sm0; sminv[n2+16] = 1.f/sm1; }

    float p0[16], p1[16];
    #pragma unroll
    for (int d = 0; d < 16; d++){ p0[d] = 0.f; p1[d] = 0.f; }
    #pragma unroll
    for (int j = 0; j < 16; j++){
        const float* vr = &Vs[m0+j][0];
        float e0 = acc0[j], e1 = acc1[j];
        #pragma unroll
        for (int d = 0; d < 16; d++){
            float vv = vr[(d+s16)&15];
            p0[d] = fmaf(e0, vv, p0[d]);
            p1[d] = fmaf(e1, vv, p1[d]);
        }
    }
    #pragma unroll
    for (int d = 0; d < 16; d++){
        p0[d] += __shfl_xor_sync(0xffffffffu, p0[d], 8);
        p1[d] += __shfl_xor_sync(0xffffffffu, p1[d], 8);
    }
    __syncthreads();
    float* red = kred;
    if (s16 < 8){
        #pragma unroll
        for (int d = 0; d < 16; d++){
            red[s16*545 + n2*17 + d]      = p0[d];
            red[s16*545 + (n2+16)*17 + d] = p1[d];
        }
    }
    __syncthreads();

    {
        int r = tid >> 3, dp = (tid & 7)*2;
        float s0 = 0.f, s1 = 0.f;
        #pragma unroll
        for (int s = 0; s < 8; s++){
            s0 += red[s*545 + r*17 + dp];
            s1 += red[s*545 + r*17 + dp + 1];
        }
        float iv = sminv[r];
        float v0 = s0*iv, v1 = s1*iv;
        size_t off = base + (size_t)(rg*32 + r)*Ee + h*16 + dp;
        __nv_bfloat16 h0 = __float2bfloat16(v0), h1 = __float2bfloat16(v1);
        __nv_bfloat162 hp; hp.x = h0; hp.y = h1;
        __nv_bfloat162 lp;
        lp.x = __float2bfloat16(v0 - __bfloat162float(h0));
        lp.y = __float2bfloat16(v1 - __bfloat162float(h1));
        *(__nv_bfloat162*)&Oh[off] = hp;
        *(__nv_bfloat162*)&Ol[off] = lp;
    }
}

// instance norm + bf16 split output; values register-cached across passes
__global__ void __launch_bounds__(256) k_inorm(
                        const float* __restrict__ X, float* __restrict__ Y,
                        const float* __restrict__ wbase, const float* __restrict__ bbase,
                        __nv_bfloat16* __restrict__ Yh, __nv_bfloat16* __restrict__ Yl)
{
    int z = blockIdx.z, b = blockIdx.x, e0 = blockIdx.y*64;
    const float* w = wbase + (size_t)z*Ee;
    const float* bp = bbase + (size_t)z*Ee;
    int tid = threadIdx.x;
    int el = tid & 63, nc = tid >> 6;
    size_t base = ((size_t)(z*Bb+b))*Nn*Ee;
    float vals[64];
    float s = 0.f, ss = 0.f;
    #pragma unroll
    for (int k = 0; k < 64; k++){
        float v = X[base + (size_t)(nc + 4*k)*Ee + e0 + el];
        vals[k] = v;
        s += v; ss += v*v;
    }
    __shared__ float sh_s[4][64], sh_ss[4][64];
    __shared__ float muA[64], invA[64];
    sh_s[nc][el] = s; sh_ss[nc][el] = ss;
    __syncthreads();
    if (nc == 0){
        float S  = sh_s[0][el]+sh_s[1][el]+sh_s[2][el]+sh_s[3][el];
        float SS = sh_ss[0][el]+sh_ss[1][el]+sh_ss[2][el]+sh_ss[3][el];
        float mu = S*(1.f/Nn);
        float var = SS*(1.f/Nn) - mu*mu;
        muA[el] = mu;
        invA[el] = rsqrtf(var + 1e-5f);
    }
    __syncthreads();
    float mu = muA[el];
    float sc = invA[el]*w[e0+el];
    float sb = bp[e0+el];
    #pragma unroll
    for (int k = 0; k < 64; k++){
        size_t off = base + (size_t)(nc + 4*k)*Ee + e0 + el;
        float y = (vals[k]-mu)*sc + sb;
        Y[off] = y;
        __nv_bfloat16 hi = __float2bfloat16(y);
        Yh[off] = hi;
        Yl[off] = __float2bfloat16(y - __bfloat162float(hi));
    }
}

// ================= host launcher =================
extern "C" void kernel_launch(void* const* d_in, const int* in_sizes, int n_in,
                              void* d_out, int out_size)
{
    const float* data      = (const float*)d_in[0];
    const float* node_rand = (const float*)d_in[1];
    const float* Wnode = (const float*)d_in[2];
    const float* bnode = (const float*)d_in[3];
    const float* Wedge = (const float*)d_in[4];
    const float* bedge = (const float*)d_in[5];
    const float* Wq    = (const float*)d_in[6];
    const float* Wk    = (const float*)d_in[7];
    const float* Wv    = (const float*)d_in[8];
    const float* Wcomb = (const float*)d_in[9];
    const float* bcomb = (const float*)d_in[10];
    const float* n1w   = (const float*)d_in[11];
    const float* n1b   = (const float*)d_in[12];
    const float* W1    = (const float*)d_in[13];
    const float* b1    = (const float*)d_in[14];
    const float* W2    = (const float*)d_in[15];
    const float* b2    = (const float*)d_in[16];
    const float* n2w   = (const float*)d_in[17];
    const float* n2b   = (const float*)d_in[18];
    const float* Wmix  = (const float*)d_in[19];

    float *scaled, *scaledT, *mn, *mx, *alpha, *beta;
    float *bufA, *bufB, *Qb, *Kb, *Vb, *t1, *o1;
    __nv_bfloat16 *xhA,*xlA,*xhB,*xlB,*oh,*ol,*o1h,*o1l,*ffh,*ffl;
    __nv_bfloat16 *wqh,*wql,*wkh,*wkl,*wvh,*wvl,*wch,*wcl,*w1h,*w1l,*w2h,*w2l;
    cudaGetSymbolAddress((void**)&scaled,  g_scaled);
    cudaGetSymbolAddress((void**)&scaledT, g_scaledT);
    cudaGetSymbolAddress((void**)&mn,      g_mn);
    cudaGetSymbolAddress((void**)&mx,      g_mx);
    cudaGetSymbolAddress((void**)&alpha,   g_alpha);
    cudaGetSymbolAddress((void**)&beta,    g_beta);
    cudaGetSymbolAddress((void**)&bufA,    g_bufA);
    cudaGetSymbolAddress((void**)&bufB,    g_bufB);
    cudaGetSymbolAddress((void**)&Qb,      g_Q);
    cudaGetSymbolAddress((void**)&Kb,      g_K);
    cudaGetSymbolAddress((void**)&Vb,      g_V);
    cudaGetSymbolAddress((void**)&t1,      g_t1);
    cudaGetSymbolAddress((void**)&o1,      g_o1);
    cudaGetSymbolAddress((void**)&xhA, g_xhA); cudaGetSymbolAddress((void**)&xlA, g_xlA);
    cudaGetSymbolAddress((void**)&xhB, g_xhB); cudaGetSymbolAddress((void**)&xlB, g_xlB);
    cudaGetSymbolAddress((void**)&oh,  g_oh);  cudaGetSymbolAddress((void**)&ol,  g_ol);
    cudaGetSymbolAddress((void**)&o1h, g_o1h); cudaGetSymbolAddress((void**)&o1l, g_o1l);
    cudaGetSymbolAddress((void**)&ffh, g_ffh); cudaGetSymbolAddress((void**)&ffl, g_ffl);
    cudaGetSymbolAddress((void**)&wqh, g_wqh); cudaGetSymbolAddress((void**)&wql, g_wql);
    cudaGetSymbolAddress((void**)&wkh, g_wkh); cudaGetSymbolAddress((void**)&wkl, g_wkl);
    cudaGetSymbolAddress((void**)&wvh, g_wvh); cudaGetSymbolAddress((void**)&wvl, g_wvl);
    cudaGetSymbolAddress((void**)&wch, g_wch); cudaGetSymbolAddress((void**)&wcl, g_wcl);
    cudaGetSymbolAddress((void**)&w1h, g_w1h); cudaGetSymbolAddress((void**)&w1l, g_w1l);
    cudaGetSymbolAddress((void**)&w2h, g_w2h); cudaGetSymbolAddress((void**)&w2l, g_w2l);

    // setup
    k_minmax<<<Bb, 256>>>(data, mn, mx);
    k_scale<<<dim3(8,8,Bb), dim3(32,8)>>>(data, mn, mx, scaled, scaledT);
    k_ab<<<dim3(Ll*2, Hh), 32>>>(Wedge, bedge, Wmix, alpha, beta);
    k_emb<<<BNE/256, 256>>>(node_rand, Wnode, bnode, bufA, xhA, xlA);
    k_tsplit_all<<<5120, dim3(32,8)>>>(Wq, Wk, Wv, Wcomb, W1, W2,
        wqh, wql, wkh, wkl, wvh, wvl, wch, wcl, w1h, w1l, w2h, w2l);

    for (int i = 0; i < Ll; i++){
        float* Xc = (i & 1) ? bufB : bufA;
        __nv_bfloat16* xhc = (i & 1) ? xhB : xhA;
        __nv_bfloat16* xlc = (i & 1) ? xlB : xlA;
        __nv_bfloat16* xhn = (i & 1) ? xhA : xhB;
        __nv_bfloat16* xln = (i & 1) ? xlA : xlB;
        float* Xn = (i == Ll-1) ? (float*)d_out : ((i & 1) ? bufA : bufB);
        size_t w256 = (size_t)i*2*65536;
        size_t w512 = (size_t)i*2*131072;
        const float* bcomb_i = bcomb + (size_t)i*2*Ee;
        const float* b1_i    = b1    + (size_t)i*2*FFh;
        const float* b2_i    = b2    + (size_t)i*2*Ee;

        k_tqkv<<<dim3(12,16,2), 128>>>(xhc, xlc,
            wqh + w256, wql + w256, wkh + w256, wkl + w256, wvh + w256, wvl + w256,
            Qb, Kb, Vb);
        k_attn<<<dim3(8, Bb*Hh, 2), 256>>>(Qb, Kb, Vb, scaled, scaledT,
            alpha + i*2*Hh, beta + i*2*Hh, oh, ol);
        k_tgemm<<<dim3(4,16,2), 128>>>(oh, ol, BNE, wch + w256, wcl + w256, 65536,
            bcomb_i, Ee, Xc, BNE, t1, nullptr, nullptr, BNE, 256, 256, 0);
        k_inorm<<<dim3(Bb,4,2), 256>>>(t1, o1, n1w + (size_t)i*2*Ee, n1b + (size_t)i*2*Ee, o1h, o1l);
        k_tgemm<<<dim3(8,16,2), 128>>>(o1h, o1l, BNE, w1h + w512, w1l + w512, 131072,
            b1_i, FFh, nullptr, 0, nullptr, ffh, ffl, BNF, 512, 256, 1);
        k_tgemm<<<dim3(4,16,2), 128>>>(ffh, ffl, BNF, w2h + w512, w2l + w512, 131072,
            b2_i, Ee, o1, BNE, t1, nullptr, nullptr, BNE, 256, 512, 0);
        k_inorm<<<dim3(Bb,4,2), 256>>>(t1, Xn, n2w + (size_t)i*2*Ee, n2b + (size_t)i*2*Ee, xhn, xln);
    }
}

// round 10
// speedup vs baseline: 2.5428x; 1.0757x over previous
#include <cuda_runtime.h>
#include <cuda_bf16.h>
#include <cstdint>

#define Bb 4
#define Nn 256
#define Ee 256
#define Hh 16
#define Dd 16
#define FFh 512
#define Ll 5
#define BNE (Bb*Nn*Ee)          // 262144
#define BNF (Bb*Nn*FFh)         // 524288

// ================= device scratch =================
__device__ float g_scaled [Bb*Nn*Nn];
__device__ float g_scaledT[Bb*Nn*Nn];
__device__ float g_mnp[32], g_mxp[32];
__device__ float g_alpha[Ll*2*Hh], g_beta[Ll*2*Hh];
__device__ float g_bufA[2*BNE], g_bufB[2*BNE];
__device__ float g_Q[2*BNE], g_K[2*BNE], g_V[2*BNE];
__device__ float g_t1[2*BNE], g_o1[2*BNE];

// bf16 split activations
__device__ __nv_bfloat16 g_xhA[2*BNE], g_xlA[2*BNE], g_xhB[2*BNE], g_xlB[2*BNE];
__device__ __nv_bfloat16 g_oh[2*BNE],  g_ol[2*BNE];
__device__ __nv_bfloat16 g_o1h[2*BNE], g_o1l[2*BNE];
__device__ __nv_bfloat16 g_ffh[2*BNF], g_ffl[2*BNF];
// bf16 split transposed weights (WT[N,K])
__device__ __nv_bfloat16 g_wqh[10*65536],  g_wql[10*65536];
__device__ __nv_bfloat16 g_wkh[10*65536],  g_wkl[10*65536];
__device__ __nv_bfloat16 g_wvh[10*65536],  g_wvl[10*65536];
__device__ __nv_bfloat16 g_wch[10*65536],  g_wcl[10*65536];
__device__ __nv_bfloat16 g_w1h[10*131072], g_w1l[10*131072];
__device__ __nv_bfloat16 g_w2h[10*131072], g_w2l[10*131072];

#if defined(__CUDA_ARCH__) && (__CUDA_ARCH__ >= 900)
#define PDL_SYNC()    cudaGridDependencySynchronize()
#define PDL_TRIGGER() cudaTriggerProgrammaticLaunchCompletion()
#else
#define PDL_SYNC()
#define PDL_TRIGGER()
#endif

// ================= small kernels =================
// 32 blocks: b = bid>>3, segment = bid&7 (8192 elems each)
__global__ void k_minmax(const float* __restrict__ data)
{
    PDL_SYNC();
    int b = blockIdx.x >> 3, seg = blockIdx.x & 7, tid = threadIdx.x;
    const float* p = data + (size_t)b*Nn*Nn + seg*8192;
    float lmn = 1e30f, lmx = -1e30f;
    #pragma unroll
    for (int i = 0; i < 32; i++){ float v = p[tid + i*256]; lmn = fminf(lmn,v); lmx = fmaxf(lmx,v); }
    __shared__ float smn[256], smx[256];
    smn[tid]=lmn; smx[tid]=lmx; __syncthreads();
    for (int s=128; s; s>>=1){ if (tid<s){ smn[tid]=fminf(smn[tid],smn[tid+s]); smx[tid]=fmaxf(smx[tid],smx[tid+s]); } __syncthreads(); }
    PDL_TRIGGER();
    if (!tid){ g_mnp[blockIdx.x]=smn[0]; g_mxp[blockIdx.x]=smx[0]; }
}

__global__ void k_scale(const float* __restrict__ data, float* __restrict__ S, float* __restrict__ ST)
{
    PDL_SYNC();
    int b = blockIdx.z;
    float m0v = 1e30f, M = -1e30f;
    #pragma unroll
    for (int j = 0; j < 8; j++){
        m0v = fminf(m0v, g_mnp[b*8+j]);
        M   = fmaxf(M,   g_mxp[b*8+j]);
    }
    float r = M - m0v; if (r == 0.f) r = 1.f;
    float inv = 1.f/r;
    __shared__ float tile[32][33];
    int n0 = blockIdx.y*32, mm0 = blockIdx.x*32;
    int tx = threadIdx.x, ty0 = threadIdx.y;
    #pragma unroll
    for (int i=0;i<4;i++){
        int ty = ty0 + i*8;
        float v = (data[((size_t)b*Nn + n0+ty)*Nn + mm0+tx] - m0v)*inv;
        S[((size_t)b*Nn + n0+ty)*Nn + mm0+tx] = v;
        tile[ty][tx] = v;
    }
    __syncthreads();
    PDL_TRIGGER();
    #pragma unroll
    for (int i=0;i<4;i++){
        int ty = ty0 + i*8;
        ST[((size_t)b*Nn + mm0+ty)*Nn + n0+tx] = tile[tx][ty];
    }
}

__global__ void k_ab(const float* __restrict__ Wedge, const float* __restrict__ bedge,
                     const float* __restrict__ Wmix, float* __restrict__ alpha, float* __restrict__ beta)
{
    PDL_SYNC();
    int ij = blockIdx.x, h = blockIdx.y, lane = threadIdx.x;
    float a = 0.f, bb = 0.f;
    for (int e = lane; e < Ee; e += 32){
        float wm = Wmix[((size_t)ij*Ee + e)*Hh + h];
        a  += Wedge[e]*wm;
        bb += bedge[e]*wm;
    }
    for (int o=16;o;o>>=1){ a += __shfl_xor_sync(0xffffffffu,a,o); bb += __shfl_xor_sync(0xffffffffu,bb,o); }
    PDL_TRIGGER();
    if (!lane){ alpha[ij*Hh+h]=a; beta[ij*Hh+h]=bb; }
}

__global__ void k_emb(const float* __restrict__ nr, const float* __restrict__ Wn,
                      const float* __restrict__ bn, float* __restrict__ X,
                      __nv_bfloat16* __restrict__ xh, __nv_bfloat16* __restrict__ xl)
{
    PDL_SYNC();
    int idx = blockIdx.x*256 + threadIdx.x;
    int e = idx & (Ee-1), bni = idx >> 8;
    float v = nr[bni]*Wn[e] + bn[e];
    PDL_TRIGGER();
    X[idx] = v; X[idx + BNE] = v;
    __nv_bfloat16 hi = __float2bfloat16(v);
    __nv_bfloat16 lo = __float2bfloat16(v - __bfloat162float(hi));
    xh[idx]=hi; xh[idx+BNE]=hi;
    xl[idx]=lo; xl[idx+BNE]=lo;
}

// merged transpose + split for all 6 weight families, one launch (5120 blocks)
__global__ void k_tsplit_all(
    const float* __restrict__ Wq, const float* __restrict__ Wk,
    const float* __restrict__ Wv, const float* __restrict__ Wc,
    const float* __restrict__ W1, const float* __restrict__ W2,
    __nv_bfloat16* wqh, __nv_bfloat16* wql,
    __nv_bfloat16* wkh, __nv_bfloat16* wkl,
    __nv_bfloat16* wvh, __nv_bfloat16* wvl,
    __nv_bfloat16* wch, __nv_bfloat16* wcl,
    __nv_bfloat16* w1h, __nv_bfloat16* w1l,
    __nv_bfloat16* w2h, __nv_bfloat16* w2l)
{
    PDL_SYNC();
    int bid = blockIdx.x;
    const float* s; __nv_bfloat16 *oh, *ol;
    int K, N, n0, k0, mat;
    if (bid < 2560){
        int type = bid / 640, loc = bid - type*640;
        mat = loc >> 6; int tile = loc & 63;
        K = 256; N = 256;
        n0 = (tile & 7)*32; k0 = (tile >> 3)*32;
        s  = (type==0?Wq:type==1?Wk:type==2?Wv:Wc);
        oh = (type==0?wqh:type==1?wkh:type==2?wvh:wch);
        ol = (type==0?wql:type==1?wkl:type==2?wvl:wcl);
    } else if (bid < 3840){
        int loc = bid - 2560;
        mat = loc >> 7; int tile = loc & 127;
        K = 256; N = 512;
        n0 = (tile & 15)*32; k0 = (tile >> 4)*32;
        s = W1; oh = w1h; ol = w1l;
    } else {
        int loc = bid - 3840;
        mat = loc >> 7; int tile = loc & 127;
        K = 512; N = 256;
        n0 = (tile & 7)*32; k0 = (tile >> 3)*32;
        s = W2; oh = w2h; ol = w2l;
    }
    s  += (size_t)mat*K*N;
    oh += (size_t)mat*K*N;
    ol += (size_t)mat*K*N;
    __shared__ float ts[32][33];
    int tx = threadIdx.x, ty = threadIdx.y;
    #pragma unroll
    for (int i=0;i<4;i++) ts[ty+i*8][tx] = s[(size_t)(k0+ty+i*8)*N + n0+tx];
    __syncthreads();
    PDL_TRIGGER();
    #pragma unroll
    for (int i=0;i<4;i++){
        int n = n0+ty+i*8, k = k0+tx;
        float v = ts[tx][ty+i*8];
        __nv_bfloat16 hi = __float2bfloat16(v);
        oh[(size_t)n*K + k] = hi;
        ol[(size_t)n*K + k] = __float2bfloat16(v - __bfloat162float(hi));
    }
}

// ================= HMMA 3xBF16 GEMM core, cp.async double-buffered =================
__device__ __forceinline__ void cp16(uint32_t dst, const void* src){
    asm volatile("cp.async.cg.shared.global [%0], [%1], 16;\n" :: "r"(dst), "l"(src));
}

__device__ __forceinline__ void hmma(float* c, const uint32_t* a, const uint32_t* b){
    asm volatile("mma.sync.aligned.m16n8k16.row.col.f32.bf16.bf16.f32 "
        "{%0,%1,%2,%3}, {%4,%5,%6,%7}, {%8,%9}, {%0,%1,%2,%3};"
        : "+f"(c[0]), "+f"(c[1]), "+f"(c[2]), "+f"(c[3])
        : "r"(a[0]), "r"(a[1]), "r"(a[2]), "r"(a[3]), "r"(b[0]), "r"(b[1]));
}

__device__ __forceinline__ void tgemm_core(
    const __nv_bfloat16* __restrict__ ah, const __nv_bfloat16* __restrict__ al,
    const __nv_bfloat16* __restrict__ wh, const __nv_bfloat16* __restrict__ wl,
    const float* __restrict__ bias, const float* __restrict__ res,
    float* __restrict__ Cf, __nv_bfloat16* __restrict__ Chi, __nv_bfloat16* __restrict__ Clo,
    int m0, int n0, int Ng, int K, int relu)
{
    __shared__ __align__(16) __nv_bfloat16 smb[2][4][64*40];  // [stage][Ah,Al,Bh,Bl]
    int tid = threadIdx.x;
    int lane = tid & 31, w = tid >> 5;
    int wm = (w >> 1)*32, wn = (w & 1)*32;
    int g = lane >> 2, tg = lane & 3;
    uint32_t sbase;
    asm("{ .reg .u64 t; cvta.to.shared.u64 t, %1; cvt.u32.u64 %0, t; }"
        : "=r"(sbase) : "l"((void*)&smb[0][0][0]));

    float acc[2][4][4];
    #pragma unroll
    for (int mi=0;mi<2;mi++)
        #pragma unroll
        for (int ni=0;ni<4;ni++)
            #pragma unroll
            for (int q=0;q<4;q++) acc[mi][ni][q]=0.f;

    const int nch = K >> 5;
    int crow = tid >> 2, cseg = (tid & 3)*8;

    auto issue = [&](int c){
        uint32_t sb2 = sbase + (uint32_t)((c & 1) ? 20480 : 0);
        int co = c*32 + cseg;
        #pragma unroll
        for (int it = 0; it < 2; it++){
            int row = crow + it*32;
            uint32_t dof = (uint32_t)((row*40 + cseg)*2);
            cp16(sb2         + dof, ah + (size_t)(m0+row)*K + co);
            cp16(sb2 + 5120  + dof, al + (size_t)(m0+row)*K + co);
            cp16(sb2 + 10240 + dof, wh + (size_t)(n0+row)*K + co);
            cp16(sb2 + 15360 + dof, wl + (size_t)(n0+row)*K + co);
        }
        asm volatile("cp.async.commit_group;\n");
    };

    issue(0);
    for (int c = 0; c < nch; c++){
        asm volatile("cp.async.wait_group 0;\n");
        __syncthreads();
        if (c + 1 < nch) issue(c + 1);
        int st = c & 1;
        const __nv_bfloat16* pA0 = &smb[st][0][0];
        const __nv_bfloat16* pA1 = &smb[st][1][0];
        const __nv_bfloat16* pB0 = &smb[st][2][0];
        const __nv_bfloat16* pB1 = &smb[st][3][0];
        #pragma unroll
        for (int ks = 0; ks < 2; ks++){
            int kb = ks*16 + 2*tg;
            uint32_t fah[2][4], fal[2][4];
            #pragma unroll
            for (int mi = 0; mi < 2; mi++){
                int rb = wm + mi*16 + g;
                fah[mi][0] = *(const uint32_t*)&pA0[rb*40 + kb];
                fah[mi][1] = *(const uint32_t*)&pA0[(rb+8)*40 + kb];
                fah[mi][2] = *(const uint32_t*)&pA0[rb*40 + kb + 8];
                fah[mi][3] = *(const uint32_t*)&pA0[(rb+8)*40 + kb + 8];
                fal[mi][0] = *(const uint32_t*)&pA1[rb*40 + kb];
                fal[mi][1] = *(const uint32_t*)&pA1[(rb+8)*40 + kb];
                fal[mi][2] = *(const uint32_t*)&pA1[rb*40 + kb + 8];
                fal[mi][3] = *(const uint32_t*)&pA1[(rb+8)*40 + kb + 8];
            }
            uint32_t fbh[4][2], fbl[4][2];
            #pragma unroll
            for (int ni = 0; ni < 4; ni++){
                int nb = wn + ni*8 + g;
                fbh[ni][0] = *(const uint32_t*)&pB0[nb*40 + kb];
                fbh[ni][1] = *(const uint32_t*)&pB0[nb*40 + kb + 8];
                fbl[ni][0] = *(const uint32_t*)&pB1[nb*40 + kb];
                fbl[ni][1] = *(const uint32_t*)&pB1[nb*40 + kb + 8];
            }
            #pragma unroll
            for (int mi = 0; mi < 2; mi++)
                #pragma unroll
                for (int ni = 0; ni < 4; ni++){
                    hmma(acc[mi][ni], fah[mi], fbh[ni]);
                    hmma(acc[mi][ni], fah[mi], fbl[ni]);
                    hmma(acc[mi][ni], fal[mi], fbh[ni]);
                }
        }
    }

    PDL_TRIGGER();
    #pragma unroll
    for (int mi = 0; mi < 2; mi++){
        #pragma unroll
        for (int ni = 0; ni < 4; ni++){
            int col = n0 + wn + ni*8 + 2*tg;
            float b0 = bias ? bias[col]   : 0.f;
            float b1 = bias ? bias[col+1] : 0.f;
            #pragma unroll
            for (int half = 0; half < 2; half++){
                int m = m0 + wm + mi*16 + g + half*8;
                float v0 = acc[mi][ni][half*2+0] + b0;
                float v1 = acc[mi][ni][half*2+1] + b1;
                if (res){
                    v0 += res[(size_t)m*Ng + col];
                    v1 += res[(size_t)m*Ng + col+1];
                }
                if (relu){ v0 = fmaxf(v0, 0.f); v1 = fmaxf(v1, 0.f); }
                if (Cf){
                    float2 o; o.x = v0; o.y = v1;
                    *(float2*)&Cf[(size_t)m*Ng + col] = o;
                }
                if (Chi){
                    __nv_bfloat16 h0 = __float2bfloat16(v0), h1 = __float2bfloat16(v1);
                    __nv_bfloat162 hp; hp.x = h0; hp.y = h1;
                    __nv_bfloat162 lp;
                    lp.x = __float2bfloat16(v0 - __bfloat162float(h0));
                    lp.y = __float2bfloat16(v1 - __bfloat162float(h1));
                    *(__nv_bfloat162*)&Chi[(size_t)m*Ng + col] = hp;
                    *(__nv_bfloat162*)&Clo[(size_t)m*Ng + col] = lp;
                }
            }
        }
    }
}

// fused QKV: grid (12, 16, 2): wsel = x>>2 (0=Q,1=K,2=V), nt = x&3
__global__ void __launch_bounds__(128) k_tqkv(
                       const __nv_bfloat16* __restrict__ xh, const __nv_bfloat16* __restrict__ xl,
                       const __nv_bfloat16* wqh, const __nv_bfloat16* wql,
                       const __nv_bfloat16* wkh, const __nv_bfloat16* wkl,
                       const __nv_bfloat16* wvh, const __nv_bfloat16* wvl,
                       float* Q, float* K, float* V)
{
    PDL_SYNC();
    int wsel = blockIdx.x >> 2, nt = blockIdx.x & 3, z = blockIdx.z;
    int az = wsel ? (1 - z) : z;
    const __nv_bfloat16 *wh, *wl; float* out;
    if (wsel == 0){ wh = wqh; wl = wql; out = Q; }
    else if (wsel == 1){ wh = wkh; wl = wkl; out = K; }
    else { wh = wvh; wl = wvl; out = V; }
    tgemm_core(xh + (size_t)az*BNE, xl + (size_t)az*BNE,
               wh + (size_t)z*65536, wl + (size_t)z*65536,
               nullptr, nullptr,
               out + (size_t)z*BNE, nullptr, nullptr,
               blockIdx.y*64, nt*64, 256, 256, 0);
}

// generic: grid (Ng/64, 16, 2)
__global__ void __launch_bounds__(128) k_tgemm(
                        const __nv_bfloat16* __restrict__ ah, const __nv_bfloat16* __restrict__ al, int aStrideZ,
                        const __nv_bfloat16* __restrict__ wh, const __nv_bfloat16* __restrict__ wl, int wStrideZ,
                        const float* bias, int biasStrideZ,
                        const float* res, int resStrideZ,
                        float* Cf, __nv_bfloat16* Chi, __nv_bfloat16* Clo, int cStrideZ,
                        int Ng, int K, int relu)
{
    PDL_SYNC();
    int z = blockIdx.z;
    tgemm_core(ah + (size_t)z*aStrideZ, al + (size_t)z*aStrideZ,
               wh + (size_t)z*wStrideZ, wl + (size_t)z*wStrideZ,
               bias ? bias + (size_t)z*biasStrideZ : nullptr,
               res  ? res  + (size_t)z*resStrideZ  : nullptr,
               Cf  ? Cf  + (size_t)z*cStrideZ : nullptr,
               Chi ? Chi + (size_t)z*cStrideZ : nullptr,
               Clo ? Clo + (size_t)z*cStrideZ : nullptr,
               blockIdx.y*64, blockIdx.x*64, Ng, K, relu);
}

// ================= fused attention: score + bias + softmax + PV =================
__global__ void __launch_bounds__(256) k_attn(
    const float* __restrict__ Q, const float* __restrict__ Kg, const float* __restrict__ Vg,
    const float* __restrict__ scaled, const float* __restrict__ scaledT,
    const float* __restrict__ alpha, const float* __restrict__ beta,
    __nv_bfloat16* __restrict__ Oh, __nv_bfloat16* __restrict__ Ol)
{
    PDL_SYNC();
    __shared__ float qs[32][17];
    __shared__ float Vs[256][17];
    __shared__ float kred[8*545];   // Ks[256][17], later red[8][545]
    __shared__ float sminv[32];

    int rg = blockIdx.x, bh = blockIdx.y, z = blockIdx.z;
    int b = bh >> 4, h = bh & 15;
    const float* Sc = z ? scaledT : scaled;
    size_t base = ((size_t)(z*Bb+b))*(size_t)Nn*Ee;
    const float* Kp = Kg + base + h*16;
    const float* Vp = Vg + base + h*16;
    const float* Qp = Q  + base + (size_t)rg*32*Ee + h*16;
    float al = alpha[z*Hh+h], be = beta[z*Hh+h];
    int tid = threadIdx.x;
    float* Ks = kred;

    {
        int m = tid, sh = m >> 4;
        const float4* kr4 = (const float4*)(Kp + (size_t)m*Ee);
        const float4* vr4 = (const float4*)(Vp + (size_t)m*Ee);
        #pragma unroll
        for (int j4 = 0; j4 < 4; j4++){
            float4 kv = kr4[j4], vv = vr4[j4];
            Ks[m*17 + ((j4*4+0+sh)&15)] = kv.x;
            Ks[m*17 + ((j4*4+1+sh)&15)] = kv.y;
            Ks[m*17 + ((j4*4+2+sh)&15)] = kv.z;
            Ks[m*17 + ((j4*4+3+sh)&15)] = kv.w;
            Vs[m][(j4*4+0+sh)&15] = vv.x;
            Vs[m][(j4*4+1+sh)&15] = vv.y;
            Vs[m][(j4*4+2+sh)&15] = vv.z;
            Vs[m][(j4*4+3+sh)&15] = vv.w;
        }
        int r = tid >> 3, dq = (tid & 7)*2;
        float2 q2 = *(const float2*)(Qp + (size_t)r*Ee + dq);
        qs[r][dq]   = q2.x*0.25f;
        qs[r][dq+1] = q2.y*0.25f;
    }
    __syncthreads();

    int n2 = tid >> 4, s16 = tid & 15;
    int m0 = s16*16;

    float q0[16], q1[16];
    #pragma unroll
    for (int d = 0; d < 16; d++){ q0[d] = qs[n2][d]; q1[d] = qs[n2+16][d]; }

    float acc0[16], acc1[16];
    {
        const float* sr0 = Sc + ((size_t)b*Nn + rg*32 + n2)*Nn + m0;
        const float* sr1 = sr0 + (size_t)16*Nn;
        #pragma unroll
        for (int j = 0; j < 16; j += 4){
            float4 v0 = *(const float4*)&sr0[j];
            acc0[j]   = fmaf(v0.x, al, be); acc0[j+1] = fmaf(v0.y, al, be);
            acc0[j+2] = fmaf(v0.z, al, be); acc0[j+3] = fmaf(v0.w, al, be);
            float4 v1 = *(const float4*)&sr1[j];
            acc1[j]   = fmaf(v1.x, al, be); acc1[j+1] = fmaf(v1.y, al, be);
            acc1[j+2] = fmaf(v1.z, al, be); acc1[j+3] = fmaf(v1.w, al, be);
        }
    }
    #pragma unroll
    for (int j = 0; j < 16; j++){
        const float* kr = &Ks[(m0+j)*17];
        float a0 = acc0[j], a1 = acc1[j];
        #pragma unroll
        for (int d = 0; d < 16; d++){
            float kv = kr[(d+s16)&15];
            a0 = fmaf(q0[d], kv, a0);
            a1 = fmaf(q1[d], kv, a1);
        }
        acc0[j] = a0; acc1[j] = a1;
    }

    float mx0 = -1e30f, mx1 = -1e30f;
    #pragma unroll
    for (int j = 0; j < 16; j++){ mx0 = fmaxf(mx0, acc0[j]); mx1 = fmaxf(mx1, acc1[j]); }
    #pragma unroll
    for (int o = 1; o < 16; o <<= 1){
        mx0 = fmaxf(mx0, __shfl_xor_sync(0xffffffffu, mx0, o));
        mx1 = fmaxf(mx1, __shfl_xor_sync(0xffffffffu, mx1, o));
    }
    float sm0 = 0.f, sm1 = 0.f;
    #pragma unroll
    for (int j = 0; j < 16; j++){
        acc0[j] = __expf(acc0[j]-mx0); sm0 += acc0[j];
        acc1[j] = __expf(acc1[j]-mx1); sm1 += acc1[j];
    }
    #pragma unroll
    for (int o = 1; o < 16; o <<= 1){
        sm0 += __shfl_xor_sync(0xffffffffu, sm0, o);
        sm1 += __shfl_xor_sync(0xffffffffu, sm1, o);
    }
    if (s16 == 0){ sminv[n2] = 1.f/sm0; sminv[n2+16] = 1.f/sm1; }

    float p0[16], p1[16];
    #pragma unroll
    for (int d = 0; d < 16; d++){ p0[d] = 0.f; p1[d] = 0.f; }
    #pragma unroll
    for (int j = 0; j < 16; j++){
        const float* vr = &Vs[m0+j][0];
        float e0 = acc0[j], e1 = acc1[j];
        #pragma unroll
        for (int d = 0; d < 16; d++){
            float vv = vr[(d+s16)&15];
            p0[d] = fmaf(e0, vv, p0[d]);
            p1[d] = fmaf(e1, vv, p1[d]);
        }
    }
    #pragma unroll
    for (int d = 0; d < 16; d++){
        p0[d] += __shfl_xor_sync(0xffffffffu, p0[d], 8);
        p1[d] += __shfl_xor_sync(0xffffffffu, p1[d], 8);
    }
    __syncthreads();
    float* red = kred;
    if (s16 < 8){
        #pragma unroll
        for (int d = 0; d < 16; d++){
            red[s16*545 + n2*17 + d]      = p0[d];
            red[s16*545 + (n2+16)*17 + d] = p1[d];
        }
    }
    __syncthreads();

    PDL_TRIGGER();
    {
        int r = tid >> 3, dp = (tid & 7)*2;
        float s0 = 0.f, s1 = 0.f;
        #pragma unroll
        for (int s = 0; s < 8; s++){
            s0 += red[s*545 + r*17 + dp];
            s1 += red[s*545 + r*17 + dp + 1];
        }
        float iv = sminv[r];
        float v0 = s0*iv, v1 = s1*iv;
        size_t off = base + (size_t)(rg*32 + r)*Ee + h*16 + dp;
        __nv_bfloat16 h0 = __float2bfloat16(v0), h1 = __float2bfloat16(v1);
        __nv_bfloat162 hp; hp.x = h0; hp.y = h1;
        __nv_bfloat162 lp;
        lp.x = __float2bfloat16(v0 - __bfloat162float(h0));
        lp.y = __float2bfloat16(v1 - __bfloat162float(h1));
        *(__nv_bfloat162*)&Oh[off] = hp;
        *(__nv_bfloat162*)&Ol[off] = lp;
    }
}

// instance norm + bf16 split; grid (Bb, 16, 2), 256 thr: 16 e x 16 n-chunks
__global__ void __launch_bounds__(256) k_inorm(
                        const float* __restrict__ X, float* __restrict__ Y,
                        const float* __restrict__ wbase, const float* __restrict__ bbase,
                        __nv_bfloat16* __restrict__ Yh, __nv_bfloat16* __restrict__ Yl)
{
    PDL_SYNC();
    int z = blockIdx.z, b = blockIdx.x, e0 = blockIdx.y*16;
    const float* w = wbase + (size_t)z*Ee;
    const float* bp = bbase + (size_t)z*Ee;
    int tid = threadIdx.x;
    int el = tid & 15, nc = tid >> 4;
    size_t base = ((size_t)(z*Bb+b))*Nn*Ee;
    float vals[16];
    float s = 0.f, ss = 0.f;
    #pragma unroll
    for (int k = 0; k < 16; k++){
        float v = X[base + (size_t)(nc + 16*k)*Ee + e0 + el];
        vals[k] = v;
        s += v; ss += v*v;
    }
    __shared__ float shs[16][17], shss[16][17];
    __shared__ float muA[16], invA[16];
    shs[nc][el] = s; shss[nc][el] = ss;
    __syncthreads();
    if (tid < 16){
        float S = 0.f, SS = 0.f;
        #pragma unroll
        for (int j = 0; j < 16; j++){ S += shs[j][tid]; SS += shss[j][tid]; }
        float mu = S*(1.f/Nn);
        float var = SS*(1.f/Nn) - mu*mu;
        muA[tid] = mu;
        invA[tid] = rsqrtf(var + 1e-5f);
    }
    __syncthreads();
    float mu = muA[el];
    float sc = invA[el]*w[e0+el];
    float sb = bp[e0+el];
    PDL_TRIGGER();
    #pragma unroll
    for (int k = 0; k < 16; k++){
        size_t off = base + (size_t)(nc + 16*k)*Ee + e0 + el;
        float y = (vals[k]-mu)*sc + sb;
        Y[off] = y;
        __nv_bfloat16 hi = __float2bfloat16(y);
        Yh[off] = hi;
        Yl[off] = __float2bfloat16(y - __bfloat162float(hi));
    }
}

// ================= host launcher =================
template <typename F, typename... A>
static inline void pdl_launch(F f, dim3 grid, dim3 block, A... args)
{
    cudaLaunchConfig_t cfg = {};
    cfg.gridDim = grid; cfg.blockDim = block;
    cfg.dynamicSmemBytes = 0; cfg.stream = 0;
    cudaLaunchAttribute at[1];
    at[0].id = cudaLaunchAttributeProgrammaticStreamSerialization;
    at[0].val.programmaticStreamSerializationAllowed = 1;
    cfg.attrs = at; cfg.numAttrs = 1;
    if (cudaLaunchKernelEx(&cfg, f, args...) != cudaSuccess)
        f<<<grid, block>>>(args...);
}

extern "C" void kernel_launch(void* const* d_in, const int* in_sizes, int n_in,
                              void* d_out, int out_size)
{
    const float* data      = (const float*)d_in[0];
    const float* node_rand = (const float*)d_in[1];
    const float* Wnode = (const float*)d_in[2];
    const float* bnode = (const float*)d_in[3];
    const float* Wedge = (const float*)d_in[4];
    const float* bedge = (const float*)d_in[5];
    const float* Wq    = (const float*)d_in[6];
    const float* Wk    = (const float*)d_in[7];
    const float* Wv    = (const float*)d_in[8];
    const float* Wcomb = (const float*)d_in[9];
    const float* bcomb = (const float*)d_in[10];
    const float* n1w   = (const float*)d_in[11];
    const float* n1b   = (const float*)d_in[12];
    const float* W1    = (const float*)d_in[13];
    const float* b1    = (const float*)d_in[14];
    const float* W2    = (const float*)d_in[15];
    const float* b2    = (const float*)d_in[16];
    const float* n2w   = (const float*)d_in[17];
    const float* n2b   = (const float*)d_in[18];
    const float* Wmix  = (const float*)d_in[19];

    float *scaled, *scaledT, *alpha, *beta;
    float *bufA, *bufB, *Qb, *Kb, *Vb, *t1, *o1;
    __nv_bfloat16 *xhA,*xlA,*xhB,*xlB,*oh,*ol,*o1h,*o1l,*ffh,*ffl;
    __nv_bfloat16 *wqh,*wql,*wkh,*wkl,*wvh,*wvl,*wch,*wcl,*w1h,*w1l,*w2h,*w2l;
    cudaGetSymbolAddress((void**)&scaled,  g_scaled);
    cudaGetSymbolAddress((void**)&scaledT, g_scaledT);
    cudaGetSymbolAddress((void**)&alpha,   g_alpha);
    cudaGetSymbolAddress((void**)&beta,    g_beta);
    cudaGetSymbolAddress((void**)&bufA,    g_bufA);
    cudaGetSymbolAddress((void**)&bufB,    g_bufB);
    cudaGetSymbolAddress((void**)&Qb,      g_Q);
    cudaGetSymbolAddress((void**)&Kb,      g_K);
    cudaGetSymbolAddress((void**)&Vb,      g_V);
    cudaGetSymbolAddress((void**)&t1,      g_t1);
    cudaGetSymbolAddress((void**)&o1,      g_o1);
    cudaGetSymbolAddress((void**)&xhA, g_xhA); cudaGetSymbolAddress((void**)&xlA, g_xlA);
    cudaGetSymbolAddress((void**)&xhB, g_xhB); cudaGetSymbolAddress((void**)&xlB, g_xlB);
    cudaGetSymbolAddress((void**)&oh,  g_oh);  cudaGetSymbolAddress((void**)&ol,  g_ol);
    cudaGetSymbolAddress((void**)&o1h, g_o1h); cudaGetSymbolAddress((void**)&o1l, g_o1l);
    cudaGetSymbolAddress((void**)&ffh, g_ffh); cudaGetSymbolAddress((void**)&ffl, g_ffl);
    cudaGetSymbolAddress((void**)&wqh, g_wqh); cudaGetSymbolAddress((void**)&wql, g_wql);
    cudaGetSymbolAddress((void**)&wkh, g_wkh); cudaGetSymbolAddress((void**)&wkl, g_wkl);
    cudaGetSymbolAddress((void**)&wvh, g_wvh); cudaGetSymbolAddress((void**)&wvl, g_wvl);
    cudaGetSymbolAddress((void**)&wch, g_wch); cudaGetSymbolAddress((void**)&wcl, g_wcl);
    cudaGetSymbolAddress((void**)&w1h, g_w1h); cudaGetSymbolAddress((void**)&w1l, g_w1l);
    cudaGetSymbolAddress((void**)&w2h, g_w2h); cudaGetSymbolAddress((void**)&w2l, g_w2l);

    // setup
    pdl_launch(k_minmax, dim3(32), dim3(256), data);
    pdl_launch(k_scale, dim3(8,8,Bb), dim3(32,8), data, scaled, scaledT);
    pdl_launch(k_ab, dim3(Ll*2, Hh), dim3(32), Wedge, bedge, Wmix, alpha, beta);
    pdl_launch(k_emb, dim3(BNE/256), dim3(256), node_rand, Wnode, bnode, bufA, xhA, xlA);
    pdl_launch(k_tsplit_all, dim3(5120), dim3(32,8), Wq, Wk, Wv, Wcomb, W1, W2,
        wqh, wql, wkh, wkl, wvh, wvl, wch, wcl, w1h, w1l, w2h, w2l);

    for (int i = 0; i < Ll; i++){
        float* Xc = (i & 1) ? bufB : bufA;
        __nv_bfloat16* xhc = (i & 1) ? xhB : xhA;
        __nv_bfloat16* xlc = (i & 1) ? xlB : xlA;
        __nv_bfloat16* xhn = (i & 1) ? xhA : xhB;
        __nv_bfloat16* xln = (i & 1) ? xlA : xlB;
        float* Xn = (i == Ll-1) ? (float*)d_out : ((i & 1) ? bufA : bufB);
        size_t w256 = (size_t)i*2*65536;
        size_t w512 = (size_t)i*2*131072;
        const float* bcomb_i = bcomb + (size_t)i*2*Ee;
        const float* b1_i    = b1    + (size_t)i*2*FFh;
        const float* b2_i    = b2    + (size_t)i*2*Ee;

        pdl_launch(k_tqkv, dim3(12,16,2), dim3(128),
            (const __nv_bfloat16*)xhc, (const __nv_bfloat16*)xlc,
            (const __nv_bfloat16*)(wqh + w256), (const __nv_bfloat16*)(wql + w256),
            (const __nv_bfloat16*)(wkh + w256), (const __nv_bfloat16*)(wkl + w256),
            (const __nv_bfloat16*)(wvh + w256), (const __nv_bfloat16*)(wvl + w256),
            Qb, Kb, Vb);
        pdl_launch(k_attn, dim3(8, Bb*Hh, 2), dim3(256),
            (const float*)Qb, (const float*)Kb, (const float*)Vb,
            (const float*)scaled, (const float*)scaledT,
            (const float*)(alpha + i*2*Hh), (const float*)(beta + i*2*Hh), oh, ol);
        pdl_launch(k_tgemm, dim3(4,16,2), dim3(128),
            (const __nv_bfloat16*)oh, (const __nv_bfloat16*)ol, (int)BNE,
            (const __nv_bfloat16*)(wch + w256), (const __nv_bfloat16*)(wcl + w256), (int)65536,
            bcomb_i, (int)Ee, (const float*)Xc, (int)BNE,
            t1, (__nv_bfloat16*)nullptr, (__nv_bfloat16*)nullptr, (int)BNE, (int)256, (int)256, (int)0);
        pdl_launch(k_inorm, dim3(Bb,16,2), dim3(256),
            (const float*)t1, o1, n1w + (size_t)i*2*Ee, n1b + (size_t)i*2*Ee, o1h, o1l);
        pdl_launch(k_tgemm, dim3(8,16,2), dim3(128),
            (const __nv_bfloat16*)o1h, (const __nv_bfloat16*)o1l, (int)BNE,
            (const __nv_bfloat16*)(w1h + w512), (const __nv_bfloat16*)(w1l + w512), (int)131072,
            b1_i, (int)FFh, (const float*)nullptr, (int)0,
            (float*)nullptr, ffh, ffl, (int)BNF, (int)512, (int)256, (int)1);
        pdl_launch(k_tgemm, dim3(4,16,2), dim3(128),
            (const __nv_bfloat16*)ffh, (const __nv_bfloat16*)ffl, (int)BNF,
            (const __nv_bfloat16*)(w2h + w512), (const __nv_bfloat16*)(w2l + w512), (int)131072,
            b2_i, (int)Ee, (const float*)o1, (int)BNE,
            t1, (__nv_bfloat16*)nullptr, (__nv_bfloat16*)nullptr, (int)BNE, (int)256, (int)512, (int)0);
        pdl_launch(k_inorm, dim3(Bb,16,2), dim3(256),
            (const float*)t1, Xn, n2w + (size_t)i*2*Ee, n2b + (size_t)i*2*Ee, xhn, xln);
    }
}